// round 6
// baseline (speedup 1.0000x reference)
#include <cuda_runtime.h>
#include <cuda_bf16.h>
#include <math.h>

#define NB 4
#define NP 2048
#define NC 128
#define ND 384
#define NH 6
#define FD 192
#define M3 (3*NP)   // 6144

// ---------------- scratch ----------------
__device__ float g_normx[NB*NC*3*NP];
__device__ float g_q [NB*ND*3*NP];
__device__ float g_k [NB*ND*3*NP];
__device__ float g_v [NB*ND*3*NP];
__device__ float g_ao[NB*ND*3*NP];
__device__ float g_G [NB*NP*1536];
__device__ float g_x5[NB*2*NC*3*NP];
__device__ float g_vnx[NB*NC*3*NP];
__device__ float g_nx2[NB*NC*3*NP];
__device__ float g_p3[NB*2*NC*3*NP];
__device__ float g_d3[NB*2*NC*3*NP];
__device__ float g_h [NB*2*NC*3*NP];
__device__ float g_p4[NB*NC*3*NP];
__device__ float g_d4[NB*NC*3*NP];
__device__ float g_cw[512*128];

__device__ __forceinline__ unsigned f2tf(float f) {
    unsigned u;
    asm("cvt.rna.tf32.f32 %0, %1;" : "=r"(u) : "f"(f));
    return u;
}
__device__ __forceinline__ float f2tff(float f) {
    return __uint_as_float(f2tf(f));
}
__device__ __forceinline__ void mma8(float* d, const unsigned* a, unsigned b0, unsigned b1) {
    asm volatile("mma.sync.aligned.m16n8k8.row.col.f32.tf32.tf32.f32 "
                 "{%0,%1,%2,%3},{%4,%5,%6,%7},{%8,%9},{%0,%1,%2,%3};"
                 : "+f"(d[0]), "+f"(d[1]), "+f"(d[2]), "+f"(d[3])
                 : "r"(a[0]), "r"(a[1]), "r"(a[2]), "r"(a[3]), "r"(b0), "r"(b1));
}

// ---------------- weight prep ----------------
__global__ void prep_cw(const float* __restrict__ W1, const float* __restrict__ U1,
                        float* __restrict__ CW)
{
    int idx = blockIdx.x * 256 + threadIdx.x;
    if (idx >= 512*128) return;
    int col = idx >> 7;
    int c   = idx & 127;
    int a = col / 128;
    int o = col % 128;
    float v;
    if      (a == 0) v = W1[o*256 + c];
    else if (a == 1) v = W1[o*256 + 128 + c] - W1[o*256 + c];
    else if (a == 2) v = U1[o*256 + c];
    else             v = U1[o*256 + 128 + c] - U1[o*256 + c];
    CW[col*128 + c] = v;
}

// ---------------- vector-norm layernorm ----------------
__global__ __launch_bounds__(128) void ln_k(const float* __restrict__ in,
                                            const float* __restrict__ g,
                                            const float* __restrict__ bb,
                                            float* __restrict__ out, int mode)
{
    int bn = blockIdx.x;
    int b = bn >> 11, n = bn & 2047;
    int c = threadIdx.x;
    float v0, v1, v2;
    if (mode == 0) {
        const float* p = in + (long long)bn*384 + 3*c;
        v0 = p[0]; v1 = p[1]; v2 = p[2];
    } else {
        const float* p = in + ((long long)b*NC + c)*M3 + n;
        v0 = p[0]; v1 = p[2048]; v2 = p[4096];
    }
    float nrm = sqrtf(v0*v0 + v1*v1 + v2*v2 + 1e-6f);
    float s = nrm, s2 = nrm*nrm;
    for (int m = 16; m; m >>= 1) {
        s  += __shfl_xor_sync(0xffffffffu, s,  m);
        s2 += __shfl_xor_sync(0xffffffffu, s2, m);
    }
    __shared__ float sb[8];
    int w = c >> 5, lane = c & 31;
    if (!lane) { sb[w] = s; sb[4 + w] = s2; }
    __syncthreads();
    float ts  = sb[0] + sb[1] + sb[2] + sb[3];
    float ts2 = sb[4] + sb[5] + sb[6] + sb[7];
    float mu  = ts * (1.f/128.f);
    float var = ts2 * (1.f/128.f) - mu*mu;
    float nhat = (nrm - mu) / sqrtf(var + 1e-5f);
    float scale = (g[c]*nhat + bb[c]) / nrm;
    float* q = out + ((long long)b*NC + c)*M3 + n;
    q[0] = v0*scale; q[2048] = v1*scale; q[4096] = v2*scale;
}

// ---------------- tf32 tensor-core batched GEMM, double-buffered ----------------
__global__ __launch_bounds__(256, 2) void gemm_k(
    const float* __restrict__ W, const float* __restrict__ X, float* __restrict__ Y,
    const float* __restrict__ Res,
    int Cin, int ldx,
    long long xsb, long long xsi, long long ysb, long long ysi,
    int oso, int osm, int zflag, int mode)
{
    __shared__ float sw[2][16*136];
    __shared__ float sx[2][16*136];
    int z = blockIdx.z;
    int b  = zflag ? z/3 : z;
    int i3 = zflag ? z%3 : 0;
    const float* xb = X + (long long)b*xsb + (long long)i3*xsi;
    float* yb = Y + (long long)b*ysb + (long long)i3*ysi;
    int m0 = blockIdx.x * 128;
    int o0 = blockIdx.y * 128;
    int tid = threadIdx.x;
    int wid = tid >> 5, lane = tid & 31;
    int a_ = lane >> 2, b_ = lane & 3;
    int wy = wid >> 1, wx = wid & 1;

    int wrow = tid >> 2, wkc = (tid & 3) << 2;
    int xkr = tid >> 5, xmc = (tid & 31) << 2;
    const float* wp0 = W + (long long)(o0 + wrow)*Cin + wkc;
    const float* wp1 = W + (long long)(o0 + 64 + wrow)*Cin + wkc;
    const float* xp0 = xb + (long long)xkr*ldx + m0 + xmc;
    const float* xp1 = xb + (long long)(xkr + 8)*ldx + m0 + xmc;

    float4 pw0 = *(const float4*)(wp0);
    float4 pw1 = *(const float4*)(wp1);
    float4 px0 = *(const float4*)(xp0);
    float4 px1 = *(const float4*)(xp1);

    float acc[2][8][4];
    #pragma unroll
    for (int i = 0; i < 2; i++)
        #pragma unroll
        for (int j = 0; j < 8; j++)
            #pragma unroll
            for (int c = 0; c < 4; c++) acc[i][j][c] = 0.f;

    int nchunk = Cin >> 4;
    for (int ch = 0; ch < nchunk; ch++) {
        int buf = ch & 1;
        float* swb = sw[buf];
        float* sxb = sx[buf];
        swb[(wkc+0)*136 + wrow] = f2tff(pw0.x);
        swb[(wkc+1)*136 + wrow] = f2tff(pw0.y);
        swb[(wkc+2)*136 + wrow] = f2tff(pw0.z);
        swb[(wkc+3)*136 + wrow] = f2tff(pw0.w);
        swb[(wkc+0)*136 + wrow + 64] = f2tff(pw1.x);
        swb[(wkc+1)*136 + wrow + 64] = f2tff(pw1.y);
        swb[(wkc+2)*136 + wrow + 64] = f2tff(pw1.z);
        swb[(wkc+3)*136 + wrow + 64] = f2tff(pw1.w);
        float4 t0 = make_float4(f2tff(px0.x), f2tff(px0.y), f2tff(px0.z), f2tff(px0.w));
        float4 t1 = make_float4(f2tff(px1.x), f2tff(px1.y), f2tff(px1.z), f2tff(px1.w));
        *(float4*)(sxb + xkr*136 + xmc) = t0;
        *(float4*)(sxb + (xkr + 8)*136 + xmc) = t1;
        __syncthreads();
        if (ch + 1 < nchunk) {
            int k0 = (ch + 1) << 4;
            pw0 = *(const float4*)(wp0 + k0);
            pw1 = *(const float4*)(wp1 + k0);
            px0 = *(const float4*)(xp0 + (long long)k0*ldx);
            px1 = *(const float4*)(xp1 + (long long)k0*ldx);
        }
        #pragma unroll
        for (int kf = 0; kf < 2; kf++) {
            const float* wp = swb + (kf*8 + b_)*136 + wy*32 + a_;
            unsigned A[2][4];
            A[0][0] = __float_as_uint(wp[0]);   A[0][1] = __float_as_uint(wp[8]);
            A[0][2] = __float_as_uint(wp[544]); A[0][3] = __float_as_uint(wp[552]);
            A[1][0] = __float_as_uint(wp[16]);  A[1][1] = __float_as_uint(wp[24]);
            A[1][2] = __float_as_uint(wp[560]); A[1][3] = __float_as_uint(wp[568]);
            const float* xp = sxb + (kf*8 + b_)*136 + wx*64 + a_;
            #pragma unroll
            for (int nf = 0; nf < 8; nf++) {
                unsigned B0 = __float_as_uint(xp[nf*8]);
                unsigned B1 = __float_as_uint(xp[nf*8 + 544]);
                mma8(acc[0][nf], A[0], B0, B1);
                mma8(acc[1][nf], A[1], B0, B1);
            }
        }
    }

    int ob = o0 + wy*32, mb = m0 + wx*64;
    if (osm == 1) {
        #pragma unroll
        for (int mf = 0; mf < 2; mf++)
            #pragma unroll
            for (int nf = 0; nf < 8; nf++) {
                int o = ob + mf*16 + a_;
                int m = mb + nf*8 + 2*b_;
                float2 v0 = make_float2(acc[mf][nf][0], acc[mf][nf][1]);
                float2 v1 = make_float2(acc[mf][nf][2], acc[mf][nf][3]);
                if (mode == 1) {
                    long long rb = (long long)b*NP*ND;
                    v0.x += Res[rb + (long long)(m & 2047)*ND + 3*o + (m >> 11)];
                    v0.y += Res[rb + (long long)((m+1) & 2047)*ND + 3*o + ((m+1) >> 11)];
                    v1.x += Res[rb + (long long)(m & 2047)*ND + 3*(o+8) + (m >> 11)];
                    v1.y += Res[rb + (long long)((m+1) & 2047)*ND + 3*(o+8) + ((m+1) >> 11)];
                }
                *(float2*)(yb + (long long)o*oso + m) = v0;
                *(float2*)(yb + (long long)(o+8)*oso + m) = v1;
            }
    } else {
        #pragma unroll
        for (int mf = 0; mf < 2; mf++)
            #pragma unroll
            for (int nf = 0; nf < 8; nf++)
                #pragma unroll
                for (int c = 0; c < 4; c++) {
                    int o = ob + mf*16 + a_ + ((c >> 1) ? 8 : 0);
                    int m = mb + nf*8 + 2*b_ + (c & 1);
                    yb[(long long)o*oso + (long long)m*osm] = acc[mf][nf][c];
                }
    }
}

// ---------------- tf32 flash attention v3: 128q tile, 64-key stream, shared KV buffer ----------------
// Qs[192][136], KVs[192][72], Ps[64][136], state
#define FTC_SMEM ((192*136 + 192*72 + 64*136 + 896)*4)

__global__ __launch_bounds__(256) void flash_tc(const float* __restrict__ Q,
                                                const float* __restrict__ K,
                                                const float* __restrict__ V,
                                                float* __restrict__ O)
{
    extern __shared__ float sm[];
    float* Qs  = sm;                    // [192][136]
    float* KVs = Qs + 192*136;          // [192][72]
    float* Ps  = KVs + 192*72;          // [64 keys][136 rows]
    float* m_s  = Ps + 64*136;          // [128]
    float* l_s  = m_s + 128;            // [128]
    float* al_s = l_s + 128;            // [128]
    float* red  = al_s + 128;           // [256]
    float* red2 = red + 256;            // [256]

    int n0 = blockIdx.x * 128;
    long long hb = (long long)(blockIdx.z*NH + blockIdx.y) * FD * NP;
    const float* Qb = Q + hb;
    const float* Kb = K + hb;
    const float* Vb = V + hb;
    float* Ob = O + hb;

    int tid = threadIdx.x;
    int wid = tid >> 5, lane = tid & 31;
    int a_ = lane >> 2, b_ = lane & 3;
    int qg = wid >> 1, kh = wid & 1;    // QK: 32q x 32k per warp
    int db = wid * 24;                  // PV: 24-dim slice per warp

    for (int idx = tid; idx < 192*32; idx += 256) {
        int d = idx >> 5, c = (idx & 31) << 2;
        float4 v = *(const float4*)(Qb + (long long)d*NP + n0 + c);
        v.x = f2tff(v.x*0.125f); v.y = f2tff(v.y*0.125f);
        v.z = f2tff(v.z*0.125f); v.w = f2tff(v.w*0.125f);
        *(float4*)(Qs + d*136 + c) = v;
    }
    if (tid < 128) { m_s[tid] = -1e30f; l_s[tid] = 0.f; }

    float o_acc[8][3][4];
    #pragma unroll
    for (int i = 0; i < 8; i++)
        #pragma unroll
        for (int j = 0; j < 3; j++)
            #pragma unroll
            for (int c = 0; c < 4; c++) o_acc[i][j][c] = 0.f;

    for (int kt = 0; kt < NP; kt += 64) {
        __syncthreads();    // prev PV done; KVs free
        for (int idx = tid; idx < 192*16; idx += 256) {
            int d = idx >> 4, c = (idx & 15) << 2;
            float4 v = *(const float4*)(Kb + (long long)d*NP + kt + c);
            v.x = f2tff(v.x); v.y = f2tff(v.y);
            v.z = f2tff(v.z); v.w = f2tff(v.w);
            *(float4*)(KVs + d*72 + c) = v;
        }
        __syncthreads();

        // ---- QK: 32q x 32k per warp ----
        float s[2][4][4];
        #pragma unroll
        for (int mf = 0; mf < 2; mf++)
            #pragma unroll
            for (int nf = 0; nf < 4; nf++)
                #pragma unroll
                for (int c = 0; c < 4; c++) s[mf][nf][c] = 0.f;
        #pragma unroll
        for (int kf = 0; kf < 24; kf++) {
            const float* qp = Qs + (kf*8 + b_)*136 + qg*32 + a_;
            unsigned A[2][4];
            A[0][0] = __float_as_uint(qp[0]);   A[0][1] = __float_as_uint(qp[8]);
            A[0][2] = __float_as_uint(qp[544]); A[0][3] = __float_as_uint(qp[552]);
            A[1][0] = __float_as_uint(qp[16]);  A[1][1] = __float_as_uint(qp[24]);
            A[1][2] = __float_as_uint(qp[560]); A[1][3] = __float_as_uint(qp[568]);
            const float* kp = KVs + (kf*8 + b_)*72 + kh*32 + a_;
            #pragma unroll
            for (int nf = 0; nf < 4; nf++) {
                unsigned B0 = __float_as_uint(kp[nf*8]);
                unsigned B1 = __float_as_uint(kp[nf*8 + 288]);
                mma8(s[0][nf], A[0], B0, B1);
                mma8(s[1][nf], A[1], B0, B1);
            }
        }

        // ---- row max ----
        #pragma unroll
        for (int r = 0; r < 4; r++) {
            int mf = r >> 1, hi = (r & 1) << 1;
            float m = fmaxf(fmaxf(s[mf][0][hi], s[mf][0][hi+1]),
                            fmaxf(s[mf][1][hi], s[mf][1][hi+1]));
            m = fmaxf(m, fmaxf(fmaxf(s[mf][2][hi], s[mf][2][hi+1]),
                               fmaxf(s[mf][3][hi], s[mf][3][hi+1])));
            m = fmaxf(m, __shfl_xor_sync(0xffffffffu, m, 1));
            m = fmaxf(m, __shfl_xor_sync(0xffffffffu, m, 2));
            if (b_ == 0)
                red[(qg*32 + mf*16 + a_ + (r & 1)*8)*2 + kh] = m;
        }
        __syncthreads();
        if (tid < 128) {
            float tm = fmaxf(red[tid*2], red[tid*2 + 1]);
            float mn = fmaxf(m_s[tid], tm);
            al_s[tid] = __expf(m_s[tid] - mn);
            m_s[tid] = mn;
        }
        __syncthreads();

        // ---- exp + Ps + psum; rescale o_acc ----
        float psum[4] = {0.f, 0.f, 0.f, 0.f};
        #pragma unroll
        for (int mf = 0; mf < 2; mf++)
            #pragma unroll
            for (int c2 = 0; c2 < 2; c2++) {
                int row = qg*32 + mf*16 + a_ + c2*8;
                float mrow = m_s[row];
                #pragma unroll
                for (int nf = 0; nf < 4; nf++)
                    #pragma unroll
                    for (int c1 = 0; c1 < 2; c1++) {
                        float p = __expf(s[mf][nf][c2*2 + c1] - mrow);
                        psum[mf*2 + c2] += p;
                        Ps[(kh*32 + nf*8 + 2*b_ + c1)*136 + row] = p;
                    }
            }
        #pragma unroll
        for (int r = 0; r < 4; r++) {
            float ps = psum[r];
            ps += __shfl_xor_sync(0xffffffffu, ps, 1);
            ps += __shfl_xor_sync(0xffffffffu, ps, 2);
            if (b_ == 0)
                red2[(qg*32 + (r >> 1)*16 + a_ + (r & 1)*8)*2 + kh] = ps;
        }
        #pragma unroll
        for (int mf8 = 0; mf8 < 8; mf8++) {
            float al0 = al_s[mf8*16 + a_];
            float al1 = al_s[mf8*16 + a_ + 8];
            #pragma unroll
            for (int nd = 0; nd < 3; nd++) {
                o_acc[mf8][nd][0] *= al0; o_acc[mf8][nd][1] *= al0;
                o_acc[mf8][nd][2] *= al1; o_acc[mf8][nd][3] *= al1;
            }
        }
        __syncthreads();    // Ps + red2 visible; K fully consumed
        if (tid < 128)
            l_s[tid] = l_s[tid]*al_s[tid] + red2[tid*2] + red2[tid*2 + 1];
        // load V into the same KV buffer
        for (int idx = tid; idx < 192*16; idx += 256) {
            int d = idx >> 4, c = (idx & 15) << 2;
            float4 u = *(const float4*)(Vb + (long long)d*NP + kt + c);
            u.x = f2tff(u.x); u.y = f2tff(u.y);
            u.z = f2tff(u.z); u.w = f2tff(u.w);
            *(float4*)(KVs + d*72 + c) = u;
        }
        __syncthreads();

        // ---- PV: all 128 q x 24-dim slice per warp ----
        #pragma unroll
        for (int kf = 0; kf < 8; kf++) {
            unsigned Bv[3][2];
            #pragma unroll
            for (int nd = 0; nd < 3; nd++) {
                const float* vp = KVs + (db + nd*8 + a_)*72 + kf*8 + b_;
                Bv[nd][0] = __float_as_uint(vp[0]);
                Bv[nd][1] = __float_as_uint(vp[4]);
            }
            const float* pp = Ps + (kf*8 + b_)*136 + a_;
            #pragma unroll
            for (int mf8 = 0; mf8 < 8; mf8++) {
                unsigned A4[4];
                A4[0] = __float_as_uint(pp[mf8*16]);
                A4[1] = __float_as_uint(pp[mf8*16 + 8]);
                A4[2] = __float_as_uint(pp[mf8*16 + 544]);
                A4[3] = __float_as_uint(pp[mf8*16 + 552]);
                mma8(o_acc[mf8][0], A4, Bv[0][0], Bv[0][1]);
                mma8(o_acc[mf8][1], A4, Bv[1][0], Bv[1][1]);
                mma8(o_acc[mf8][2], A4, Bv[2][0], Bv[2][1]);
            }
        }
    }

    __syncthreads();
    if (tid < 128) al_s[tid] = 1.f / l_s[tid];
    __syncthreads();
    #pragma unroll
    for (int mf8 = 0; mf8 < 8; mf8++) {
        float i0 = al_s[mf8*16 + a_];
        float i1 = al_s[mf8*16 + a_ + 8];
        #pragma unroll
        for (int nd = 0; nd < 3; nd++) {
            int d0 = db + nd*8 + 2*b_;
            long long r0 = (long long)d0*NP + n0 + mf8*16 + a_;
            Ob[r0]            = o_acc[mf8][nd][0] * i0;
            Ob[r0 + NP]       = o_acc[mf8][nd][1] * i0;
            Ob[r0 + 8]        = o_acc[mf8][nd][2] * i1;
            Ob[r0 + NP + 8]   = o_acc[mf8][nd][3] * i1;
        }
    }
}

// ---------------- kNN gather + VN-leaky + mean pool ----------------
__global__ __launch_bounds__(128) void gather_leaky(const float* __restrict__ G,
                                                    const int* __restrict__ knn,
                                                    float* __restrict__ X5)
{
    int bn = blockIdx.x;
    int b = bn >> 11, n = bn & 2047;
    int o = threadIdx.x;
    __shared__ int ridx[8];
    if (o < 8) ridx[o] = knn[((b*8 + o) << 11) + n];
    __syncthreads();
    const float* gc = G + (long long)bn*1536;
    float pc0 = gc[128 + o],        dc0 = gc[384 + o];
    float pc1 = gc[512 + 128 + o],  dc1 = gc[512 + 384 + o];
    float pc2 = gc[1024 + 128 + o], dc2 = gc[1024 + 384 + o];
    float a0 = 0.f, a1 = 0.f, a2 = 0.f;
    #pragma unroll
    for (int k = 0; k < 8; k++) {
        const float* gr = G + (long long)ridx[k]*1536;
        float p0 = gr[o] + pc0;
        float p1 = gr[512 + o] + pc1;
        float p2 = gr[1024 + o] + pc2;
        float d0 = gr[256 + o] + dc0;
        float d1 = gr[512 + 256 + o] + dc1;
        float d2 = gr[1024 + 256 + o] + dc2;
        float dot = p0*d0 + p1*d1 + p2*d2;
        if (dot < 0.f) {
            float f = 0.8f * dot / (d0*d0 + d1*d1 + d2*d2 + 1e-6f);
            p0 -= f*d0; p1 -= f*d1; p2 -= f*d2;
        }
        a0 += p0; a1 += p1; a2 += p2;
    }
    float* y = X5 + (long long)b*(2*NC*M3) + (long long)(128 + o)*M3 + n;
    y[0] = a0*0.125f; y[2048] = a1*0.125f; y[4096] = a2*0.125f;
}

// ---------------- elementwise VN-leaky ----------------
__global__ void leaky_ew(const float* __restrict__ P, const float* __restrict__ D,
                         float* __restrict__ Y)
{
    int idx = blockIdx.x*256 + threadIdx.x;
    int n = idx & 2047;
    int bo = idx >> 11;
    long long base = ((long long)bo*3 << 11) + n;
    float p0 = P[base], p1 = P[base + 2048], p2 = P[base + 4096];
    float d0 = D[base], d1 = D[base + 2048], d2 = D[base + 4096];
    float dot = p0*d0 + p1*d1 + p2*d2;
    if (dot < 0.f) {
        float f = 0.8f * dot / (d0*d0 + d1*d1 + d2*d2 + 1e-6f);
        p0 -= f*d0; p1 -= f*d1; p2 -= f*d2;
    }
    Y[base] = p0; Y[base + 2048] = p1; Y[base + 4096] = p2;
}

// ---------------- conv4 leaky + residual + output transpose ----------------
__global__ void final_k(const float* __restrict__ P, const float* __restrict__ D,
                        const float* __restrict__ vnx, float* __restrict__ out)
{
    int idx = blockIdx.x*256 + threadIdx.x;
    int n = idx & 2047;
    int o = (idx >> 11) & 127;
    int b = idx >> 18;
    long long base2 = (((long long)(b*NC + o))*3 << 11) + n;
    float p0 = P[base2], p1 = P[base2 + 2048], p2 = P[base2 + 4096];
    float d0 = D[base2], d1 = D[base2 + 2048], d2 = D[base2 + 4096];
    float dot = p0*d0 + p1*d1 + p2*d2;
    if (dot < 0.f) {
        float f = 0.8f * dot / (d0*d0 + d1*d1 + d2*d2 + 1e-6f);
        p0 -= f*d0; p1 -= f*d1; p2 -= f*d2;
    }
    float r0 = vnx[base2], r1 = vnx[base2 + 2048], r2 = vnx[base2 + 4096];
    float* q = out + ((long long)(b*NP + n))*ND + 3*o;
    q[0] = r0 + p0; q[1] = r1 + p1; q[2] = r2 + p2;
}

// ---------------- host ----------------
extern "C" void kernel_launch(void* const* d_in, const int* in_sizes, int n_in,
                              void* d_out, int out_size)
{
    (void)in_sizes; (void)n_in; (void)out_size;
    const float* x  = (const float*)d_in[0];
    const int* knn  = (const int*)d_in[1];
    const float* g1 = (const float*)d_in[2];
    const float* b1 = (const float*)d_in[3];
    const float* g2 = (const float*)d_in[4];
    const float* b2 = (const float*)d_in[5];
    const float* Wq = (const float*)d_in[6];
    const float* Wk = (const float*)d_in[7];
    const float* Wv = (const float*)d_in[8];
    const float* Wo = (const float*)d_in[9];
    const float* W1 = (const float*)d_in[10];
    const float* U1 = (const float*)d_in[11];
    const float* W2 = (const float*)d_in[12];
    const float* W3 = (const float*)d_in[13];
    const float* U3 = (const float*)d_in[14];
    const float* W4 = (const float*)d_in[15];
    const float* U4 = (const float*)d_in[16];
    float* out = (float*)d_out;

    float *normx,*q,*k,*v,*ao,*G,*x5,*vnx,*nx2,*p3,*d3,*h,*p4,*d4,*cw;
    cudaGetSymbolAddress((void**)&normx, g_normx);
    cudaGetSymbolAddress((void**)&q,  g_q);
    cudaGetSymbolAddress((void**)&k,  g_k);
    cudaGetSymbolAddress((void**)&v,  g_v);
    cudaGetSymbolAddress((void**)&ao, g_ao);
    cudaGetSymbolAddress((void**)&G,  g_G);
    cudaGetSymbolAddress((void**)&x5, g_x5);
    cudaGetSymbolAddress((void**)&vnx, g_vnx);
    cudaGetSymbolAddress((void**)&nx2, g_nx2);
    cudaGetSymbolAddress((void**)&p3, g_p3);
    cudaGetSymbolAddress((void**)&d3, g_d3);
    cudaGetSymbolAddress((void**)&h,  g_h);
    cudaGetSymbolAddress((void**)&p4, g_p4);
    cudaGetSymbolAddress((void**)&d4, g_d4);
    cudaGetSymbolAddress((void**)&cw, g_cw);

    cudaFuncSetAttribute(flash_tc, cudaFuncAttributeMaxDynamicSharedMemorySize, FTC_SMEM);

    prep_cw<<<256, 256>>>(W1, U1, cw);
    ln_k<<<NB*NP, 128>>>(x, g1, b1, normx, 0);

    long long sN = (long long)NC*M3;
    long long sQ = (long long)ND*M3;
    long long sX5 = (long long)2*NC*M3;

    gemm_k<<<dim3(48,3,NB), 256>>>(Wq, normx, q, nullptr, 128, M3, sN, 0, sQ, 0, M3, 1, 0, 0);
    gemm_k<<<dim3(48,3,NB), 256>>>(Wk, normx, k, nullptr, 128, M3, sN, 0, sQ, 0, M3, 1, 0, 0);
    gemm_k<<<dim3(48,3,NB), 256>>>(Wv, normx, v, nullptr, 128, M3, sN, 0, sQ, 0, M3, 1, 0, 0);

    flash_tc<<<dim3(16, NH, NB), 256, FTC_SMEM>>>(q, k, v, ao);

    gemm_k<<<dim3(48,1,NB), 256>>>(Wo, ao, x5, nullptr, 384, M3, sQ, 0, sX5, 0, M3, 1, 0, 0);

    gemm_k<<<dim3(16,4,12), 256>>>(cw, normx, G, nullptr, 128, M3,
                                   sN, 2048, (long long)NP*1536, 512, 1, 1536, 1, 0);
    gather_leaky<<<NB*NP, 128>>>(G, knn, x5);

    gemm_k<<<dim3(48,1,NB), 256>>>(W2, x5, vnx, x, 256, M3, sX5, 0, sN, 0, M3, 1, 0, 1);

    ln_k<<<NB*NP, 128>>>(vnx, g2, b2, nx2, 1);

    gemm_k<<<dim3(48,2,NB), 256>>>(W3, nx2, p3, nullptr, 128, M3, sN, 0, sX5, 0, M3, 1, 0, 0);
    gemm_k<<<dim3(48,2,NB), 256>>>(U3, nx2, d3, nullptr, 128, M3, sN, 0, sX5, 0, M3, 1, 0, 0);
    leaky_ew<<<NB*2*NC*NP/256, 256>>>(p3, d3, h);

    gemm_k<<<dim3(48,1,NB), 256>>>(W4, h, p4, nullptr, 256, M3, sX5, 0, sN, 0, M3, 1, 0, 0);
    gemm_k<<<dim3(48,1,NB), 256>>>(U4, h, d4, nullptr, 256, M3, sX5, 0, sN, 0, M3, 1, 0, 0);

    final_k<<<NB*NC*NP/256, 256>>>(p4, d4, vnx, out);
}

// round 7
// speedup vs baseline: 1.2411x; 1.2411x over previous
#include <cuda_runtime.h>
#include <math.h>

#define NB 4
#define NP 2048
#define NC 128
#define ND 384
#define NH 6
#define FD 192
#define M3 (3*NP)

__device__ float g_normx[NB*NC*3*NP];
__device__ float g_q [NB*ND*3*NP];
__device__ float g_k [NB*ND*3*NP];
__device__ float g_v [NB*ND*3*NP];
__device__ float g_ao[NB*ND*3*NP];
__device__ float g_G [NB*NP*1536];
__device__ float g_x5[NB*2*NC*3*NP];
__device__ float g_vnx[NB*NC*3*NP];
__device__ float g_nx2[NB*NC*3*NP];
__device__ float g_p3[NB*2*NC*3*NP];
__device__ float g_d3[NB*2*NC*3*NP];
__device__ float g_h [NB*2*NC*3*NP];
__device__ float g_p4[NB*NC*3*NP];
__device__ float g_d4[NB*NC*3*NP];
__device__ float g_cw[512*128];
__device__ float g_wr[360448];

__device__ __forceinline__ unsigned f2tf(float f) {
    unsigned u;
    asm("cvt.rna.tf32.f32 %0, %1;" : "=r"(u) : "f"(f));
    return u;
}
__device__ __forceinline__ float f2tff(float f) { return __uint_as_float(f2tf(f)); }
__device__ __forceinline__ void mma8(float* d, const unsigned* a, unsigned b0, unsigned b1) {
    asm volatile("mma.sync.aligned.m16n8k8.row.col.f32.tf32.tf32.f32 "
                 "{%0,%1,%2,%3},{%4,%5,%6,%7},{%8,%9},{%0,%1,%2,%3};"
                 : "+f"(d[0]), "+f"(d[1]), "+f"(d[2]), "+f"(d[3])
                 : "r"(a[0]), "r"(a[1]), "r"(a[2]), "r"(a[3]), "r"(b0), "r"(b1));
}
__device__ __forceinline__ void cpa16(unsigned dst, const void* src) {
    asm volatile("cp.async.cg.shared.global [%0], [%1], 16;" :: "r"(dst), "l"(src));
}
__device__ __forceinline__ void cpac() { asm volatile("cp.async.commit_group;"); }
__device__ __forceinline__ void cpaw1() { asm volatile("cp.async.wait_group 1;"); }

// ---------------- weight prep: round all GEMM weights to tf32 ----------------
__global__ void prep_w(const float* __restrict__ Wq, const float* __restrict__ Wk,
                       const float* __restrict__ Wv, const float* __restrict__ Wo,
                       const float* __restrict__ W2, const float* __restrict__ W3,
                       const float* __restrict__ U3, const float* __restrict__ W4,
                       const float* __restrict__ U4, float* __restrict__ wr)
{
    int i = blockIdx.x*256 + threadIdx.x;
    if (i >= 360448) return;
    float v;
    if      (i < 49152)  v = Wq[i];
    else if (i < 98304)  v = Wk[i - 49152];
    else if (i < 147456) v = Wv[i - 98304];
    else if (i < 196608) v = Wo[i - 147456];
    else if (i < 229376) v = W2[i - 196608];
    else if (i < 262144) v = W3[i - 229376];
    else if (i < 294912) v = U3[i - 262144];
    else if (i < 327680) v = W4[i - 294912];
    else                 v = U4[i - 327680];
    wr[i] = f2tff(v);
}

__global__ void prep_cw(const float* __restrict__ W1, const float* __restrict__ U1,
                        float* __restrict__ CW)
{
    int idx = blockIdx.x * 256 + threadIdx.x;
    if (idx >= 512*128) return;
    int col = idx >> 7, c = idx & 127;
    int a = col / 128, o = col % 128;
    float v;
    if      (a == 0) v = W1[o*256 + c];
    else if (a == 1) v = W1[o*256 + 128 + c] - W1[o*256 + c];
    else if (a == 2) v = U1[o*256 + c];
    else             v = U1[o*256 + 128 + c] - U1[o*256 + c];
    CW[col*128 + c] = f2tff(v);
}

// ---------------- vector-norm layernorm (tf32-rounded output) ----------------
__global__ __launch_bounds__(128) void ln_k(const float* __restrict__ in,
                                            const float* __restrict__ g,
                                            const float* __restrict__ bb,
                                            float* __restrict__ out, int mode)
{
    int bn = blockIdx.x;
    int b = bn >> 11, n = bn & 2047;
    int c = threadIdx.x;
    float v0, v1, v2;
    if (mode == 0) {
        const float* p = in + (long long)bn*384 + 3*c;
        v0 = p[0]; v1 = p[1]; v2 = p[2];
    } else {
        const float* p = in + ((long long)b*NC + c)*M3 + n;
        v0 = p[0]; v1 = p[2048]; v2 = p[4096];
    }
    float nrm = sqrtf(v0*v0 + v1*v1 + v2*v2 + 1e-6f);
    float s = nrm, s2 = nrm*nrm;
    for (int m = 16; m; m >>= 1) {
        s  += __shfl_xor_sync(0xffffffffu, s,  m);
        s2 += __shfl_xor_sync(0xffffffffu, s2, m);
    }
    __shared__ float sb[8];
    int w = c >> 5, lane = c & 31;
    if (!lane) { sb[w] = s; sb[4 + w] = s2; }
    __syncthreads();
    float ts  = sb[0] + sb[1] + sb[2] + sb[3];
    float ts2 = sb[4] + sb[5] + sb[6] + sb[7];
    float mu  = ts * (1.f/128.f);
    float var = ts2 * (1.f/128.f) - mu*mu;
    float nhat = (nrm - mu) / sqrtf(var + 1e-5f);
    float scale = (g[c]*nhat + bb[c]) / nrm;
    float* q = out + ((long long)b*NC + c)*M3 + n;
    q[0] = f2tff(v0*scale); q[2048] = f2tff(v1*scale); q[4096] = f2tff(v2*scale);
}

// ---------------- GEMM v3: BK=32, cp.async double buffer, no in-loop cvt ----------------
// sw [128][36] per buf (4608 fl), sx [32][136] per buf (4352 fl)
#define GSMEM ((2*4608 + 2*4352)*4)
__global__ __launch_bounds__(256, 2) void gemm_k(
    const float* __restrict__ W, const float* __restrict__ X, float* __restrict__ Y,
    const float* __restrict__ Res,
    int Cin, int ldx,
    long long xsb, long long xsi, long long ysb, long long ysi,
    int oso, int osm, int zflag, int mode, float oscale)
{
    extern __shared__ float smn[];
    int z = blockIdx.z;
    int b  = zflag ? z/3 : z;
    int i3 = zflag ? z%3 : 0;
    const float* xb = X + (long long)b*xsb + (long long)i3*xsi;
    float* yb = Y + (long long)b*ysb + (long long)i3*ysi;
    int m0 = blockIdx.x * 128;
    int o0 = blockIdx.y * 128;
    int tid = threadIdx.x;
    int wid = tid >> 5, lane = tid & 31;
    int a_ = lane >> 2, b_ = lane & 3;
    int wy = wid >> 1, wx = wid & 1;
    unsigned sm_u = (unsigned)__cvta_generic_to_shared(smn);

    float acc[2][8][4];
    #pragma unroll
    for (int i = 0; i < 2; i++)
        #pragma unroll
        for (int j = 0; j < 8; j++)
            #pragma unroll
            for (int c = 0; c < 4; c++) acc[i][j][c] = 0.f;

    int nchunk = Cin >> 5;
    int fo = tid >> 3, fk4 = (tid & 7) << 2;      // W fill
    int fr = tid >> 5, fc4 = (tid & 31) << 2;     // X fill

    #define GFILL(ch, buf) do { \
        int k0 = (ch) << 5; \
        unsigned swu = sm_u + (unsigned)((buf)*4608*4); \
        unsigned sxu = sm_u + (unsigned)((9216 + (buf)*4352)*4); \
        cpa16(swu + (unsigned)((fo*36 + fk4)*4),        W + (long long)(o0 + fo)*Cin + k0 + fk4); \
        cpa16(swu + (unsigned)(((fo+32)*36 + fk4)*4),   W + (long long)(o0 + fo + 32)*Cin + k0 + fk4); \
        cpa16(swu + (unsigned)(((fo+64)*36 + fk4)*4),   W + (long long)(o0 + fo + 64)*Cin + k0 + fk4); \
        cpa16(swu + (unsigned)(((fo+96)*36 + fk4)*4),   W + (long long)(o0 + fo + 96)*Cin + k0 + fk4); \
        cpa16(sxu + (unsigned)((fr*136 + fc4)*4),       xb + (long long)(k0 + fr)*ldx + m0 + fc4); \
        cpa16(sxu + (unsigned)(((fr+8)*136 + fc4)*4),   xb + (long long)(k0 + fr + 8)*ldx + m0 + fc4); \
        cpa16(sxu + (unsigned)(((fr+16)*136 + fc4)*4),  xb + (long long)(k0 + fr + 16)*ldx + m0 + fc4); \
        cpa16(sxu + (unsigned)(((fr+24)*136 + fc4)*4),  xb + (long long)(k0 + fr + 24)*ldx + m0 + fc4); \
    } while (0)

    GFILL(0, 0); cpac();
    if (nchunk > 1) GFILL(1, 1);
    cpac();

    for (int ch = 0; ch < nchunk; ch++) {
        cpaw1();
        __syncthreads();
        int buf = ch & 1;
        const float* swb = smn + buf*4608;
        const float* sxb = smn + 9216 + buf*4352;
        const float* pA0 = swb + (wy*32 + a_)*36 + b_;
        const float* pA1 = pA0 + 576;               // +16 o rows
        const float* pX  = sxb + b_*136 + wx*64 + a_;
        #pragma unroll
        for (int kf = 0; kf < 4; kf++) {
            unsigned A[2][4];
            A[0][0] = __float_as_uint(pA0[kf*8]);
            A[0][1] = __float_as_uint(pA0[kf*8 + 288]);
            A[0][2] = __float_as_uint(pA0[kf*8 + 4]);
            A[0][3] = __float_as_uint(pA0[kf*8 + 292]);
            A[1][0] = __float_as_uint(pA1[kf*8]);
            A[1][1] = __float_as_uint(pA1[kf*8 + 288]);
            A[1][2] = __float_as_uint(pA1[kf*8 + 4]);
            A[1][3] = __float_as_uint(pA1[kf*8 + 292]);
            #pragma unroll
            for (int nf = 0; nf < 8; nf++) {
                unsigned B0 = __float_as_uint(pX[kf*1088 + nf*8]);
                unsigned B1 = __float_as_uint(pX[kf*1088 + nf*8 + 544]);
                mma8(acc[0][nf], A[0], B0, B1);
                mma8(acc[1][nf], A[1], B0, B1);
            }
        }
        __syncthreads();
        if (ch + 2 < nchunk) GFILL(ch + 2, buf);
        cpac();
    }

    int ob = o0 + wy*32, mb = m0 + wx*64;
    if (osm == 1) {
        #pragma unroll
        for (int mf = 0; mf < 2; mf++)
            #pragma unroll
            for (int nf = 0; nf < 8; nf++) {
                int o = ob + mf*16 + a_;
                int m = mb + nf*8 + 2*b_;
                float2 v0 = make_float2(acc[mf][nf][0], acc[mf][nf][1]);
                float2 v1 = make_float2(acc[mf][nf][2], acc[mf][nf][3]);
                if (mode & 1) {
                    long long rb = (long long)b*NP*ND;
                    v0.x += Res[rb + (long long)(m & 2047)*ND + 3*o + (m >> 11)];
                    v0.y += Res[rb + (long long)((m+1) & 2047)*ND + 3*o + ((m+1) >> 11)];
                    v1.x += Res[rb + (long long)(m & 2047)*ND + 3*(o+8) + (m >> 11)];
                    v1.y += Res[rb + (long long)((m+1) & 2047)*ND + 3*(o+8) + ((m+1) >> 11)];
                }
                if (mode & 2) {
                    v0.x = f2tff(v0.x*oscale); v0.y = f2tff(v0.y*oscale);
                    v1.x = f2tff(v1.x*oscale); v1.y = f2tff(v1.y*oscale);
                }
                *(float2*)(yb + (long long)o*oso + m) = v0;
                *(float2*)(yb + (long long)(o+8)*oso + m) = v1;
            }
    } else {
        #pragma unroll
        for (int mf = 0; mf < 2; mf++)
            #pragma unroll
            for (int nf = 0; nf < 8; nf++)
                #pragma unroll
                for (int c = 0; c < 4; c++) {
                    int o = ob + mf*16 + a_ + ((c >> 1) ? 8 : 0);
                    int m = mb + nf*8 + 2*b_ + (c & 1);
                    yb[(long long)o*oso + (long long)m*osm] = acc[mf][nf][c];
                }
    }
}

// ---------------- flash v4: Q swz [192][128]; 32-key dbl-buffered K/V cp.async ----------------
#define OFF_KS  24576
#define OFF_VS  36864
#define OFF_PS  50688
#define OFF_AL  55040
#define OFF_RED 55168
#define OFF_RED2 55424
#define FTC_SMEM (55680*4)

__global__ __launch_bounds__(256, 1) void flash_tc(const float* __restrict__ Q,
                                                   const float* __restrict__ K,
                                                   const float* __restrict__ V,
                                                   float* __restrict__ O)
{
    extern __shared__ float sm[];
    float* Qs   = sm;
    float* Ps   = sm + OFF_PS;
    float* al_s = sm + OFF_AL;
    float* red  = sm + OFF_RED;
    float* red2 = sm + OFF_RED2;
    unsigned sm_u = (unsigned)__cvta_generic_to_shared(sm);

    int n0 = blockIdx.x * 128;
    long long hb = (long long)(blockIdx.z*NH + blockIdx.y) * FD * NP;
    const float* Qb = Q + hb;
    const float* Kb = K + hb;
    const float* Vb = V + hb;
    float* Ob = O + hb;

    int tid = threadIdx.x;
    int wid = tid >> 5, lane = tid & 31;
    int a_ = lane >> 2, b_ = lane & 3;
    int qg = wid >> 1, kh = wid & 1;
    int db = wid * 24;

    int fd8 = tid >> 3, ft4 = (tid & 7) << 2;     // KV fill indices
    #define FKV(t, bi) do { \
        int kt = (t) << 5; \
        unsigned ku = sm_u + (unsigned)((OFF_KS + (bi)*6144)*4); \
        unsigned vu = sm_u + (unsigned)((OFF_VS + (bi)*6912)*4); \
        _Pragma("unroll") \
        for (int i = 0; i < 6; i++) { \
            int d = fd8 + i*32; \
            cpa16(ku + (unsigned)(((d << 5) + (ft4 ^ ((d & 3) << 3)))*4), Kb + (long long)d*NP + kt + ft4); \
            cpa16(vu + (unsigned)((d*36 + ft4)*4),                        Vb + (long long)d*NP + kt + ft4); \
        } \
    } while (0)

    // Q fill (swizzled) + KV(0) = group0; KV(1) = group1
    {
        int qd = tid >> 5, qc4 = (tid & 31) << 2;
        #pragma unroll
        for (int i = 0; i < 24; i++) {
            int d = qd + i*8;
            cpa16(sm_u + (unsigned)(((d << 7) + (qc4 ^ ((d & 3) << 3)))*4),
                  Qb + (long long)d*NP + n0 + qc4);
        }
    }
    FKV(0, 0); cpac();
    FKV(1, 1); cpac();

    float m_run[4] = {-1e30f, -1e30f, -1e30f, -1e30f};
    float l_run[4] = {0.f, 0.f, 0.f, 0.f};
    float o_acc[8][3][4];
    #pragma unroll
    for (int i = 0; i < 8; i++)
        #pragma unroll
        for (int j = 0; j < 3; j++)
            #pragma unroll
            for (int c = 0; c < 4; c++) o_acc[i][j][c] = 0.f;

    int s8 = b_ << 3;
    int qv00 = ((qg<<5) + a_) ^ s8;
    int qv01 = ((qg<<5) + 8 + a_) ^ s8;
    int qv10 = ((qg<<5) + 16 + a_) ^ s8;
    int qv11 = ((qg<<5) + 24 + a_) ^ s8;
    int tv0 = ((kh<<4) + a_) ^ s8;
    int tv1 = ((kh<<4) + 8 + a_) ^ s8;
    const float* pQ = Qs + (b_ << 7);
    const float* pP = Ps + b_*136 + a_;

    for (int t = 0; t < 64; t++) {
        cpaw1();
        __syncthreads();
        int bi = t & 1;
        const float* Ksb = sm + OFF_KS + bi*6144;
        const float* Vsb = sm + OFF_VS + bi*6912;
        const float* pK = Ksb + (b_ << 5);

        float s[2][2][4];
        #pragma unroll
        for (int mf = 0; mf < 2; mf++)
            #pragma unroll
            for (int nf = 0; nf < 2; nf++)
                #pragma unroll
                for (int c = 0; c < 4; c++) s[mf][nf][c] = 0.f;
        #pragma unroll
        for (int kf = 0; kf < 24; kf++) {
            unsigned A0[4], A1[4];
            int qb2 = kf << 10;
            A0[0] = __float_as_uint(pQ[qb2 + qv00]);
            A0[1] = __float_as_uint(pQ[qb2 + qv01]);
            A0[2] = __float_as_uint(pQ[qb2 + 512 + qv00]);
            A0[3] = __float_as_uint(pQ[qb2 + 512 + qv01]);
            A1[0] = __float_as_uint(pQ[qb2 + qv10]);
            A1[1] = __float_as_uint(pQ[qb2 + qv11]);
            A1[2] = __float_as_uint(pQ[qb2 + 512 + qv10]);
            A1[3] = __float_as_uint(pQ[qb2 + 512 + qv11]);
            int kb2 = kf << 8;
            unsigned B00 = __float_as_uint(pK[kb2 + tv0]);
            unsigned B01 = __float_as_uint(pK[kb2 + 128 + tv0]);
            unsigned B10 = __float_as_uint(pK[kb2 + tv1]);
            unsigned B11 = __float_as_uint(pK[kb2 + 128 + tv1]);
            mma8(s[0][0], A0, B00, B01);
            mma8(s[1][0], A1, B00, B01);
            mma8(s[0][1], A0, B10, B11);
            mma8(s[1][1], A1, B10, B11);
        }

        #pragma unroll
        for (int r = 0; r < 4; r++) {
            int mf = r >> 1, hi = (r & 1) << 1;
            float m = fmaxf(fmaxf(s[mf][0][hi], s[mf][0][hi+1]),
                            fmaxf(s[mf][1][hi], s[mf][1][hi+1]));
            m = fmaxf(m, __shfl_xor_sync(0xffffffffu, m, 1));
            m = fmaxf(m, __shfl_xor_sync(0xffffffffu, m, 2));
            if (b_ == 0)
                red[((qg<<5) + mf*16 + ((r & 1) << 3) + a_)*2 + kh] = m;
        }
        __syncthreads();

        float alpha[4];
        #pragma unroll
        for (int r = 0; r < 4; r++) {
            int row = (qg<<5) + (r >> 1)*16 + ((r & 1) << 3) + a_;
            float tm = fmaxf(red[row*2], red[row*2 + 1]);
            float mn = fmaxf(m_run[r], tm);
            alpha[r] = __expf(m_run[r] - mn);
            m_run[r] = mn;
            if (kh == 0 && b_ == 0) al_s[row] = alpha[r];
        }
        float psum[4] = {0.f, 0.f, 0.f, 0.f};
        #pragma unroll
        for (int mf = 0; mf < 2; mf++)
            #pragma unroll
            for (int c2 = 0; c2 < 2; c2++) {
                int row = (qg<<5) + mf*16 + (c2 << 3) + a_;
                float mrow = m_run[mf*2 + c2];
                #pragma unroll
                for (int nf = 0; nf < 2; nf++)
                    #pragma unroll
                    for (int c1 = 0; c1 < 2; c1++) {
                        float p = __expf(s[mf][nf][c2*2 + c1] - mrow);
                        psum[mf*2 + c2] += p;
                        Ps[((kh<<4) + nf*8 + 2*b_ + c1)*136 + row] = p;
                    }
            }
        #pragma unroll
        for (int r = 0; r < 4; r++) {
            float ps = psum[r];
            ps += __shfl_xor_sync(0xffffffffu, ps, 1);
            ps += __shfl_xor_sync(0xffffffffu, ps, 2);
            if (b_ == 0)
                red2[((qg<<5) + (r >> 1)*16 + ((r & 1) << 3) + a_)*2 + kh] = ps;
        }
        __syncthreads();

        #pragma unroll
        for (int r = 0; r < 4; r++) {
            int row = (qg<<5) + (r >> 1)*16 + ((r & 1) << 3) + a_;
            l_run[r] = l_run[r]*alpha[r] + red2[row*2] + red2[row*2 + 1];
        }
        #pragma unroll
        for (int mf8 = 0; mf8 < 8; mf8++) {
            float al0 = al_s[mf8*16 + a_];
            float al1 = al_s[mf8*16 + 8 + a_];
            #pragma unroll
            for (int nd = 0; nd < 3; nd++) {
                o_acc[mf8][nd][0] *= al0; o_acc[mf8][nd][1] *= al0;
                o_acc[mf8][nd][2] *= al1; o_acc[mf8][nd][3] *= al1;
            }
        }

        #pragma unroll
        for (int kf = 0; kf < 4; kf++) {
            unsigned Bv[3][2];
            #pragma unroll
            for (int nd = 0; nd < 3; nd++) {
                const float* vp = Vsb + (db + nd*8 + a_)*36 + b_;
                Bv[nd][0] = __float_as_uint(vp[kf*8]);
                Bv[nd][1] = __float_as_uint(vp[kf*8 + 4]);
            }
            #pragma unroll
            for (int mf8 = 0; mf8 < 8; mf8++) {
                unsigned A4[4];
                A4[0] = __float_as_uint(pP[kf*1088 + mf8*16]);
                A4[1] = __float_as_uint(pP[kf*1088 + mf8*16 + 8]);
                A4[2] = __float_as_uint(pP[kf*1088 + mf8*16 + 544]);
                A4[3] = __float_as_uint(pP[kf*1088 + mf8*16 + 552]);
                mma8(o_acc[mf8][0], A4, Bv[0][0], Bv[0][1]);
                mma8(o_acc[mf8][1], A4, Bv[1][0], Bv[1][1]);
                mma8(o_acc[mf8][2], A4, Bv[2][0], Bv[2][1]);
            }
        }
        __syncthreads();
        if (t + 2 < 64) FKV(t + 2, bi);
        cpac();
    }

    if (kh == 0 && b_ == 0) {
        #pragma unroll
        for (int r = 0; r < 4; r++)
            al_s[(qg<<5) + (r >> 1)*16 + ((r & 1) << 3) + a_] = 1.f / l_run[r];
    }
    __syncthreads();
    #pragma unroll
    for (int mf8 = 0; mf8 < 8; mf8++) {
        float i0 = al_s[mf8*16 + a_];
        float i1 = al_s[mf8*16 + 8 + a_];
        #pragma unroll
        for (int nd = 0; nd < 3; nd++) {
            int d0 = db + nd*8 + 2*b_;
            long long r0 = (long long)d0*NP + n0 + mf8*16 + a_;
            Ob[r0]          = f2tff(o_acc[mf8][nd][0] * i0);
            Ob[r0 + NP]     = f2tff(o_acc[mf8][nd][1] * i0);
            Ob[r0 + 8]      = f2tff(o_acc[mf8][nd][2] * i1);
            Ob[r0 + NP + 8] = f2tff(o_acc[mf8][nd][3] * i1);
        }
    }
}

// ---------------- kNN gather + VN-leaky + mean pool (rounded out) ----------------
__global__ __launch_bounds__(128) void gather_leaky(const float* __restrict__ G,
                                                    const int* __restrict__ knn,
                                                    float* __restrict__ X5)
{
    int bn = blockIdx.x;
    int b = bn >> 11, n = bn & 2047;
    int o = threadIdx.x;
    __shared__ int ridx[8];
    if (o < 8) ridx[o] = knn[((b*8 + o) << 11) + n];
    __syncthreads();
    const float* gc = G + (long long)bn*1536;
    float pc0 = gc[128 + o],        dc0 = gc[384 + o];
    float pc1 = gc[512 + 128 + o],  dc1 = gc[512 + 384 + o];
    float pc2 = gc[1024 + 128 + o], dc2 = gc[1024 + 384 + o];
    float a0 = 0.f, a1 = 0.f, a2 = 0.f;
    #pragma unroll
    for (int k = 0; k < 8; k++) {
        const float* gr = G + (long long)ridx[k]*1536;
        float p0 = gr[o] + pc0;
        float p1 = gr[512 + o] + pc1;
        float p2 = gr[1024 + o] + pc2;
        float d0 = gr[256 + o] + dc0;
        float d1 = gr[512 + 256 + o] + dc1;
        float d2 = gr[1024 + 256 + o] + dc2;
        float dot = p0*d0 + p1*d1 + p2*d2;
        if (dot < 0.f) {
            float f = 0.8f * dot / (d0*d0 + d1*d1 + d2*d2 + 1e-6f);
            p0 -= f*d0; p1 -= f*d1; p2 -= f*d2;
        }
        a0 += p0; a1 += p1; a2 += p2;
    }
    float* y = X5 + (long long)b*(2*NC*M3) + (long long)(128 + o)*M3 + n;
    y[0] = f2tff(a0*0.125f); y[2048] = f2tff(a1*0.125f); y[4096] = f2tff(a2*0.125f);
}

// ---------------- elementwise VN-leaky (rounded out) ----------------
__global__ void leaky_ew(const float* __restrict__ P, const float* __restrict__ D,
                         float* __restrict__ Y)
{
    int idx = blockIdx.x*256 + threadIdx.x;
    int n = idx & 2047;
    int bo = idx >> 11;
    long long base = ((long long)bo*3 << 11) + n;
    float p0 = P[base], p1 = P[base + 2048], p2 = P[base + 4096];
    float d0 = D[base], d1 = D[base + 2048], d2 = D[base + 4096];
    float dot = p0*d0 + p1*d1 + p2*d2;
    if (dot < 0.f) {
        float f = 0.8f * dot / (d0*d0 + d1*d1 + d2*d2 + 1e-6f);
        p0 -= f*d0; p1 -= f*d1; p2 -= f*d2;
    }
    Y[base] = f2tff(p0); Y[base + 2048] = f2tff(p1); Y[base + 4096] = f2tff(p2);
}

// ---------------- conv4 leaky + residual + output transpose ----------------
__global__ void final_k(const float* __restrict__ P, const float* __restrict__ D,
                        const float* __restrict__ vnx, float* __restrict__ out)
{
    int idx = blockIdx.x*256 + threadIdx.x;
    int n = idx & 2047;
    int o = (idx >> 11) & 127;
    int b = idx >> 18;
    long long base2 = (((long long)(b*NC + o))*3 << 11) + n;
    float p0 = P[base2], p1 = P[base2 + 2048], p2 = P[base2 + 4096];
    float d0 = D[base2], d1 = D[base2 + 2048], d2 = D[base2 + 4096];
    float dot = p0*d0 + p1*d1 + p2*d2;
    if (dot < 0.f) {
        float f = 0.8f * dot / (d0*d0 + d1*d1 + d2*d2 + 1e-6f);
        p0 -= f*d0; p1 -= f*d1; p2 -= f*d2;
    }
    float r0 = vnx[base2], r1 = vnx[base2 + 2048], r2 = vnx[base2 + 4096];
    float* q = out + ((long long)(b*NP + n))*ND + 3*o;
    q[0] = r0 + p0; q[1] = r1 + p1; q[2] = r2 + p2;
}

// ---------------- host ----------------
extern "C" void kernel_launch(void* const* d_in, const int* in_sizes, int n_in,
                              void* d_out, int out_size)
{
    (void)in_sizes; (void)n_in; (void)out_size;
    const float* x  = (const float*)d_in[0];
    const int* knn  = (const int*)d_in[1];
    const float* g1 = (const float*)d_in[2];
    const float* b1 = (const float*)d_in[3];
    const float* g2 = (const float*)d_in[4];
    const float* b2 = (const float*)d_in[5];
    const float* Wq = (const float*)d_in[6];
    const float* Wk = (const float*)d_in[7];
    const float* Wv = (const float*)d_in[8];
    const float* Wo = (const float*)d_in[9];
    const float* W1 = (const float*)d_in[10];
    const float* U1 = (const float*)d_in[11];
    const float* W2 = (const float*)d_in[12];
    const float* W3 = (const float*)d_in[13];
    const float* U3 = (const float*)d_in[14];
    const float* W4 = (const float*)d_in[15];
    const float* U4 = (const float*)d_in[16];
    float* out = (float*)d_out;

    float *normx,*q,*k,*v,*ao,*G,*x5,*vnx,*nx2,*p3,*d3,*h,*p4,*d4,*cw,*wr;
    cudaGetSymbolAddress((void**)&normx, g_normx);
    cudaGetSymbolAddress((void**)&q,  g_q);
    cudaGetSymbolAddress((void**)&k,  g_k);
    cudaGetSymbolAddress((void**)&v,  g_v);
    cudaGetSymbolAddress((void**)&ao, g_ao);
    cudaGetSymbolAddress((void**)&G,  g_G);
    cudaGetSymbolAddress((void**)&x5, g_x5);
    cudaGetSymbolAddress((void**)&vnx, g_vnx);
    cudaGetSymbolAddress((void**)&nx2, g_nx2);
    cudaGetSymbolAddress((void**)&p3, g_p3);
    cudaGetSymbolAddress((void**)&d3, g_d3);
    cudaGetSymbolAddress((void**)&h,  g_h);
    cudaGetSymbolAddress((void**)&p4, g_p4);
    cudaGetSymbolAddress((void**)&d4, g_d4);
    cudaGetSymbolAddress((void**)&cw, g_cw);
    cudaGetSymbolAddress((void**)&wr, g_wr);

    cudaFuncSetAttribute(flash_tc, cudaFuncAttributeMaxDynamicSharedMemorySize, FTC_SMEM);
    cudaFuncSetAttribute(gemm_k, cudaFuncAttributeMaxDynamicSharedMemorySize, GSMEM);

    prep_w<<<1408, 256>>>(Wq, Wk, Wv, Wo, W2, W3, U3, W4, U4, wr);
    prep_cw<<<256, 256>>>(W1, U1, cw);
    ln_k<<<NB*NP, 128>>>(x, g1, b1, normx, 0);

    long long sN = (long long)NC*M3;
    long long sQ = (long long)ND*M3;
    long long sX5 = (long long)2*NC*M3;

    gemm_k<<<dim3(48,3,NB), 256, GSMEM>>>(wr + 0,      normx, q, nullptr, 128, M3, sN, 0, sQ, 0, M3, 1, 0, 2, 0.125f);
    gemm_k<<<dim3(48,3,NB), 256, GSMEM>>>(wr + 49152,  normx, k, nullptr, 128, M3, sN, 0, sQ, 0, M3, 1, 0, 2, 1.0f);
    gemm_k<<<dim3(48,3,NB), 256, GSMEM>>>(wr + 98304,  normx, v, nullptr, 128, M3, sN, 0, sQ, 0, M3, 1, 0, 2, 1.0f);

    flash_tc<<<dim3(16, NH, NB), 256, FTC_SMEM>>>(q, k, v, ao);

    gemm_k<<<dim3(48,1,NB), 256, GSMEM>>>(wr + 147456, ao, x5, nullptr, 384, M3, sQ, 0, sX5, 0, M3, 1, 0, 2, 1.0f);

    gemm_k<<<dim3(16,4,12), 256, GSMEM>>>(cw, normx, G, nullptr, 128, M3,
                                          sN, 2048, (long long)NP*1536, 512, 1, 1536, 1, 0, 1.0f);
    gather_leaky<<<NB*NP, 128>>>(G, knn, x5);

    gemm_k<<<dim3(48,1,NB), 256, GSMEM>>>(wr + 196608, x5, vnx, x, 256, M3, sX5, 0, sN, 0, M3, 1, 0, 1, 1.0f);

    ln_k<<<NB*NP, 128>>>(vnx, g2, b2, nx2, 1);

    gemm_k<<<dim3(48,2,NB), 256, GSMEM>>>(wr + 229376, nx2, p3, nullptr, 128, M3, sN, 0, sX5, 0, M3, 1, 0, 0, 1.0f);
    gemm_k<<<dim3(48,2,NB), 256, GSMEM>>>(wr + 262144, nx2, d3, nullptr, 128, M3, sN, 0, sX5, 0, M3, 1, 0, 0, 1.0f);
    leaky_ew<<<NB*2*NC*NP/256, 256>>>(p3, d3, h);

    gemm_k<<<dim3(48,1,NB), 256, GSMEM>>>(wr + 294912, h, p4, nullptr, 256, M3, sX5, 0, sN, 0, M3, 1, 0, 0, 1.0f);
    gemm_k<<<dim3(48,1,NB), 256, GSMEM>>>(wr + 327680, h, d4, nullptr, 256, M3, sX5, 0, sN, 0, M3, 1, 0, 0, 1.0f);

    final_k<<<NB*NC*NP/256, 256>>>(p4, d4, vnx, out);
}

// round 8
// speedup vs baseline: 1.2753x; 1.0276x over previous
#include <cuda_runtime.h>
#include <math.h>

#define NB 4
#define NP 2048
#define NC 128
#define ND 384
#define NH 6
#define FD 192
#define M3 (3*NP)
#define QOFF (NB*ND*M3)   // 9437184

__device__ float g_normx[NB*NC*3*NP];
__device__ float g_qkv[3*NB*ND*3*NP];
__device__ float g_ao[NB*ND*3*NP];
__device__ float g_G [NB*NP*1536];
__device__ float g_x5[NB*2*NC*3*NP];
__device__ float g_vnx[NB*NC*3*NP];
__device__ float g_nx2[NB*NC*3*NP];
__device__ float g_p3[NB*2*NC*3*NP];
__device__ float g_d3[NB*2*NC*3*NP];
__device__ float g_h [NB*2*NC*3*NP];
__device__ float g_p4[NB*NC*3*NP];
__device__ float g_d4[NB*NC*3*NP];
__device__ float g_cw[512*128];
__device__ float g_wr[360448];

__device__ __forceinline__ unsigned f2tf(float f) {
    unsigned u;
    asm("cvt.rna.tf32.f32 %0, %1;" : "=r"(u) : "f"(f));
    return u;
}
__device__ __forceinline__ float f2tff(float f) { return __uint_as_float(f2tf(f)); }
__device__ __forceinline__ float fexp2(float x) {
    float r;
    asm("ex2.approx.f32 %0, %1;" : "=f"(r) : "f"(x));
    return r;
}
__device__ __forceinline__ void mma8(float* d, const unsigned* a, unsigned b0, unsigned b1) {
    asm volatile("mma.sync.aligned.m16n8k8.row.col.f32.tf32.tf32.f32 "
                 "{%0,%1,%2,%3},{%4,%5,%6,%7},{%8,%9},{%0,%1,%2,%3};"
                 : "+f"(d[0]), "+f"(d[1]), "+f"(d[2]), "+f"(d[3])
                 : "r"(a[0]), "r"(a[1]), "r"(a[2]), "r"(a[3]), "r"(b0), "r"(b1));
}
__device__ __forceinline__ void cpa16(unsigned dst, const void* src) {
    asm volatile("cp.async.cg.shared.global [%0], [%1], 16;" :: "r"(dst), "l"(src));
}
__device__ __forceinline__ void cpac() { asm volatile("cp.async.commit_group;"); }
__device__ __forceinline__ void cpaw1() { asm volatile("cp.async.wait_group 1;"); }

// ---------------- weight prep ----------------
__global__ void prep_w(const float* __restrict__ Wq, const float* __restrict__ Wk,
                       const float* __restrict__ Wv, const float* __restrict__ Wo,
                       const float* __restrict__ W2, const float* __restrict__ W3,
                       const float* __restrict__ U3, const float* __restrict__ W4,
                       const float* __restrict__ U4, float* __restrict__ wr)
{
    int i = blockIdx.x*256 + threadIdx.x;
    if (i >= 360448) return;
    float v;
    if      (i < 49152)  v = Wq[i];
    else if (i < 98304)  v = Wk[i - 49152];
    else if (i < 147456) v = Wv[i - 98304];
    else if (i < 196608) v = Wo[i - 147456];
    else if (i < 229376) v = W2[i - 196608];
    else if (i < 262144) v = W3[i - 229376];
    else if (i < 294912) v = U3[i - 262144];
    else if (i < 327680) v = W4[i - 294912];
    else                 v = U4[i - 327680];
    wr[i] = f2tff(v);
}

__global__ void prep_cw(const float* __restrict__ W1, const float* __restrict__ U1,
                        float* __restrict__ CW)
{
    int idx = blockIdx.x * 256 + threadIdx.x;
    if (idx >= 512*128) return;
    int col = idx >> 7, c = idx & 127;
    int a = col / 128, o = col % 128;
    float v;
    if      (a == 0) v = W1[o*256 + c];
    else if (a == 1) v = W1[o*256 + 128 + c] - W1[o*256 + c];
    else if (a == 2) v = U1[o*256 + c];
    else             v = U1[o*256 + 128 + c] - U1[o*256 + c];
    CW[col*128 + c] = f2tff(v);
}

// ---------------- vector-norm layernorm (tf32-rounded output) ----------------
__global__ __launch_bounds__(128) void ln_k(const float* __restrict__ in,
                                            const float* __restrict__ g,
                                            const float* __restrict__ bb,
                                            float* __restrict__ out, int mode)
{
    int bn = blockIdx.x;
    int b = bn >> 11, n = bn & 2047;
    int c = threadIdx.x;
    float v0, v1, v2;
    if (mode == 0) {
        const float* p = in + (long long)bn*384 + 3*c;
        v0 = p[0]; v1 = p[1]; v2 = p[2];
    } else {
        const float* p = in + ((long long)b*NC + c)*M3 + n;
        v0 = p[0]; v1 = p[2048]; v2 = p[4096];
    }
    float nrm = sqrtf(v0*v0 + v1*v1 + v2*v2 + 1e-6f);
    float s = nrm, s2 = nrm*nrm;
    for (int m = 16; m; m >>= 1) {
        s  += __shfl_xor_sync(0xffffffffu, s,  m);
        s2 += __shfl_xor_sync(0xffffffffu, s2, m);
    }
    __shared__ float sb[8];
    int w = c >> 5, lane = c & 31;
    if (!lane) { sb[w] = s; sb[4 + w] = s2; }
    __syncthreads();
    float ts  = sb[0] + sb[1] + sb[2] + sb[3];
    float ts2 = sb[4] + sb[5] + sb[6] + sb[7];
    float mu  = ts * (1.f/128.f);
    float var = ts2 * (1.f/128.f) - mu*mu;
    float nhat = (nrm - mu) / sqrtf(var + 1e-5f);
    float scale = (g[c]*nhat + bb[c]) / nrm;
    float* q = out + ((long long)b*NC + c)*M3 + n;
    q[0] = f2tff(v0*scale); q[2048] = f2tff(v1*scale); q[4096] = f2tff(v2*scale);
}

// ---------------- GEMM v4: BK=32, 3-stage cp.async, single sync per chunk ----------------
// stage layout: [W 128x36 (4608 fl) | X 32x136 (4352 fl)] x 3 stages = 26880 fl
#define GSMEM (26880*4)
__global__ __launch_bounds__(256, 2) void gemm_k(
    const float* __restrict__ W, const float* __restrict__ Wb,
    const float* __restrict__ X, float* __restrict__ Y, float* __restrict__ Y2,
    const float* __restrict__ Res,
    int Cin, int ldx,
    long long xsb, long long xsi, long long ysb, long long ysi,
    int oso, int osm, int zflag, int mode, float oscale, int ysplit)
{
    extern __shared__ float smn[];
    int z = blockIdx.z;
    int b  = (zflag == 1) ? z/3 : z;
    int i3 = (zflag == 1) ? z%3 : 0;
    const float* xb = X + (long long)b*xsb + (long long)i3*xsi;
    int by = blockIdx.y;
    int o0;
    float* yb;
    float osc = oscale;
    if (zflag == 2) {
        int wsel = by / 3;
        o0 = (by % 3) * 128;
        W += wsel * 49152;
        yb = Y + (long long)wsel*QOFF + (long long)b*ysb;
        if (wsel) osc = 1.0f;
    } else if (ysplit > 0 && by >= ysplit) {
        o0 = (by - ysplit) * 128;
        W = Wb;
        yb = Y2 + (long long)b*ysb + (long long)i3*ysi;
    } else {
        o0 = by * 128;
        yb = Y + (long long)b*ysb + (long long)i3*ysi;
    }
    int m0 = blockIdx.x * 128;
    int tid = threadIdx.x;
    int wid = tid >> 5, lane = tid & 31;
    int a_ = lane >> 2, b_ = lane & 3;
    int wy = wid >> 1, wx = wid & 1;
    unsigned sm_u = (unsigned)__cvta_generic_to_shared(smn);

    float acc[2][8][4];
    #pragma unroll
    for (int i = 0; i < 2; i++)
        #pragma unroll
        for (int j = 0; j < 8; j++)
            #pragma unroll
            for (int c = 0; c < 4; c++) acc[i][j][c] = 0.f;

    int nchunk = Cin >> 5;
    int fo = tid >> 3, fk4 = (tid & 7) << 2;
    int fr = tid >> 5, fc4 = (tid & 31) << 2;

    #define GFILL(ch) do { \
        int k0 = (ch) << 5; \
        int stg = (ch) % 3; \
        unsigned swu = sm_u + (unsigned)(stg*8960*4); \
        unsigned sxu = swu + (unsigned)(4608*4); \
        cpa16(swu + (unsigned)((fo*36 + fk4)*4),        W + (long long)(o0 + fo)*Cin + k0 + fk4); \
        cpa16(swu + (unsigned)(((fo+32)*36 + fk4)*4),   W + (long long)(o0 + fo + 32)*Cin + k0 + fk4); \
        cpa16(swu + (unsigned)(((fo+64)*36 + fk4)*4),   W + (long long)(o0 + fo + 64)*Cin + k0 + fk4); \
        cpa16(swu + (unsigned)(((fo+96)*36 + fk4)*4),   W + (long long)(o0 + fo + 96)*Cin + k0 + fk4); \
        cpa16(sxu + (unsigned)((fr*136 + fc4)*4),       xb + (long long)(k0 + fr)*ldx + m0 + fc4); \
        cpa16(sxu + (unsigned)(((fr+8)*136 + fc4)*4),   xb + (long long)(k0 + fr + 8)*ldx + m0 + fc4); \
        cpa16(sxu + (unsigned)(((fr+16)*136 + fc4)*4),  xb + (long long)(k0 + fr + 16)*ldx + m0 + fc4); \
        cpa16(sxu + (unsigned)(((fr+24)*136 + fc4)*4),  xb + (long long)(k0 + fr + 24)*ldx + m0 + fc4); \
    } while (0)

    GFILL(0); cpac();
    if (nchunk > 1) GFILL(1);
    cpac();

    for (int ch = 0; ch < nchunk; ch++) {
        cpaw1();
        __syncthreads();
        int stg = ch % 3;
        const float* swb = smn + stg*8960;
        const float* sxb = swb + 4608;
        const float* pA0 = swb + (wy*32 + a_)*36 + b_;
        const float* pA1 = pA0 + 576;
        const float* pX  = sxb + b_*136 + wx*64 + a_;
        #pragma unroll
        for (int kf = 0; kf < 4; kf++) {
            unsigned A[2][4];
            A[0][0] = __float_as_uint(pA0[kf*8]);
            A[0][1] = __float_as_uint(pA0[kf*8 + 288]);
            A[0][2] = __float_as_uint(pA0[kf*8 + 4]);
            A[0][3] = __float_as_uint(pA0[kf*8 + 292]);
            A[1][0] = __float_as_uint(pA1[kf*8]);
            A[1][1] = __float_as_uint(pA1[kf*8 + 288]);
            A[1][2] = __float_as_uint(pA1[kf*8 + 4]);
            A[1][3] = __float_as_uint(pA1[kf*8 + 292]);
            #pragma unroll
            for (int nf = 0; nf < 8; nf++) {
                unsigned B0 = __float_as_uint(pX[kf*1088 + nf*8]);
                unsigned B1 = __float_as_uint(pX[kf*1088 + nf*8 + 544]);
                mma8(acc[0][nf], A[0], B0, B1);
                mma8(acc[1][nf], A[1], B0, B1);
            }
        }
        if (ch + 2 < nchunk) GFILL(ch + 2);
        cpac();
    }

    int ob = o0 + wy*32, mb = m0 + wx*64;
    if (osm == 1) {
        #pragma unroll
        for (int mf = 0; mf < 2; mf++)
            #pragma unroll
            for (int nf = 0; nf < 8; nf++) {
                int o = ob + mf*16 + a_;
                int m = mb + nf*8 + 2*b_;
                float2 v0 = make_float2(acc[mf][nf][0], acc[mf][nf][1]);
                float2 v1 = make_float2(acc[mf][nf][2], acc[mf][nf][3]);
                if (mode & 1) {
                    long long rb = (long long)b*NP*ND;
                    v0.x += Res[rb + (long long)(m & 2047)*ND + 3*o + (m >> 11)];
                    v0.y += Res[rb + (long long)((m+1) & 2047)*ND + 3*o + ((m+1) >> 11)];
                    v1.x += Res[rb + (long long)(m & 2047)*ND + 3*(o+8) + (m >> 11)];
                    v1.y += Res[rb + (long long)((m+1) & 2047)*ND + 3*(o+8) + ((m+1) >> 11)];
                }
                if (mode & 2) {
                    v0.x = f2tff(v0.x*osc); v0.y = f2tff(v0.y*osc);
                    v1.x = f2tff(v1.x*osc); v1.y = f2tff(v1.y*osc);
                }
                *(float2*)(yb + (long long)o*oso + m) = v0;
                *(float2*)(yb + (long long)(o+8)*oso + m) = v1;
            }
    } else {
        #pragma unroll
        for (int mf = 0; mf < 2; mf++)
            #pragma unroll
            for (int nf = 0; nf < 8; nf++)
                #pragma unroll
                for (int c = 0; c < 4; c++) {
                    int o = ob + mf*16 + a_ + ((c >> 1) ? 8 : 0);
                    int m = mb + nf*8 + 2*b_ + (c & 1);
                    yb[(long long)o*oso + (long long)m*osm] = acc[mf][nf][c];
                }
    }
}

// ---------------- flash v4.1: exp2-folded softmax ----------------
#define OFF_KS  24576
#define OFF_VS  36864
#define OFF_PS  50688
#define OFF_AL  55040
#define OFF_RED 55168
#define OFF_RED2 55424
#define FTC_SMEM (55680*4)

__global__ __launch_bounds__(256, 1) void flash_tc(const float* __restrict__ Q,
                                                   const float* __restrict__ K,
                                                   const float* __restrict__ V,
                                                   float* __restrict__ O)
{
    extern __shared__ float sm[];
    float* Qs   = sm;
    float* Ps   = sm + OFF_PS;
    float* al_s = sm + OFF_AL;
    float* red  = sm + OFF_RED;
    float* red2 = sm + OFF_RED2;
    unsigned sm_u = (unsigned)__cvta_generic_to_shared(sm);

    int n0 = blockIdx.x * 128;
    long long hb = (long long)(blockIdx.z*NH + blockIdx.y) * FD * NP;
    const float* Qb = Q + hb;
    const float* Kb = K + hb;
    const float* Vb = V + hb;
    float* Ob = O + hb;

    int tid = threadIdx.x;
    int wid = tid >> 5, lane = tid & 31;
    int a_ = lane >> 2, b_ = lane & 3;
    int qg = wid >> 1, kh = wid & 1;
    int db = wid * 24;

    int fd8 = tid >> 3, ft4 = (tid & 7) << 2;
    #define FKV(t, bi) do { \
        int kt = (t) << 5; \
        unsigned ku = sm_u + (unsigned)((OFF_KS + (bi)*6144)*4); \
        unsigned vu = sm_u + (unsigned)((OFF_VS + (bi)*6912)*4); \
        _Pragma("unroll") \
        for (int i = 0; i < 6; i++) { \
            int d = fd8 + i*32; \
            cpa16(ku + (unsigned)(((d << 5) + (ft4 ^ ((d & 3) << 3)))*4), Kb + (long long)d*NP + kt + ft4); \
            cpa16(vu + (unsigned)((d*36 + ft4)*4),                        Vb + (long long)d*NP + kt + ft4); \
        } \
    } while (0)

    {
        int qd = tid >> 5, qc4 = (tid & 31) << 2;
        #pragma unroll
        for (int i = 0; i < 24; i++) {
            int d = qd + i*8;
            cpa16(sm_u + (unsigned)(((d << 7) + (qc4 ^ ((d & 3) << 3)))*4),
                  Qb + (long long)d*NP + n0 + qc4);
        }
    }
    FKV(0, 0); cpac();
    FKV(1, 1); cpac();

    float m_run[4] = {-1e30f, -1e30f, -1e30f, -1e30f};
    float l_run[4] = {0.f, 0.f, 0.f, 0.f};
    float o_acc[8][3][4];
    #pragma unroll
    for (int i = 0; i < 8; i++)
        #pragma unroll
        for (int j = 0; j < 3; j++)
            #pragma unroll
            for (int c = 0; c < 4; c++) o_acc[i][j][c] = 0.f;

    int s8 = b_ << 3;
    int qv00 = ((qg<<5) + a_) ^ s8;
    int qv01 = ((qg<<5) + 8 + a_) ^ s8;
    int qv10 = ((qg<<5) + 16 + a_) ^ s8;
    int qv11 = ((qg<<5) + 24 + a_) ^ s8;
    int tv0 = ((kh<<4) + a_) ^ s8;
    int tv1 = ((kh<<4) + 8 + a_) ^ s8;
    const float* pQ = Qs + (b_ << 7);
    const float* pP = Ps + b_*136 + a_;

    for (int t = 0; t < 64; t++) {
        cpaw1();
        __syncthreads();
        int bi = t & 1;
        const float* Ksb = sm + OFF_KS + bi*6144;
        const float* Vsb = sm + OFF_VS + bi*6912;
        const float* pK = Ksb + (b_ << 5);

        float s[2][2][4];
        #pragma unroll
        for (int mf = 0; mf < 2; mf++)
            #pragma unroll
            for (int nf = 0; nf < 2; nf++)
                #pragma unroll
                for (int c = 0; c < 4; c++) s[mf][nf][c] = 0.f;
        #pragma unroll
        for (int kf = 0; kf < 24; kf++) {
            unsigned A0[4], A1[4];
            int qb2 = kf << 10;
            A0[0] = __float_as_uint(pQ[qb2 + qv00]);
            A0[1] = __float_as_uint(pQ[qb2 + qv01]);
            A0[2] = __float_as_uint(pQ[qb2 + 512 + qv00]);
            A0[3] = __float_as_uint(pQ[qb2 + 512 + qv01]);
            A1[0] = __float_as_uint(pQ[qb2 + qv10]);
            A1[1] = __float_as_uint(pQ[qb2 + qv11]);
            A1[2] = __float_as_uint(pQ[qb2 + 512 + qv10]);
            A1[3] = __float_as_uint(pQ[qb2 + 512 + qv11]);
            int kb2 = kf << 8;
            unsigned B00 = __float_as_uint(pK[kb2 + tv0]);
            unsigned B01 = __float_as_uint(pK[kb2 + 128 + tv0]);
            unsigned B10 = __float_as_uint(pK[kb2 + tv1]);
            unsigned B11 = __float_as_uint(pK[kb2 + 128 + tv1]);
            mma8(s[0][0], A0, B00, B01);
            mma8(s[1][0], A1, B00, B01);
            mma8(s[0][1], A0, B10, B11);
            mma8(s[1][1], A1, B10, B11);
        }

        #pragma unroll
        for (int r = 0; r < 4; r++) {
            int mf = r >> 1, hi = (r & 1) << 1;
            float m = fmaxf(fmaxf(s[mf][0][hi], s[mf][0][hi+1]),
                            fmaxf(s[mf][1][hi], s[mf][1][hi+1]));
            m = fmaxf(m, __shfl_xor_sync(0xffffffffu, m, 1));
            m = fmaxf(m, __shfl_xor_sync(0xffffffffu, m, 2));
            if (b_ == 0)
                red[((qg<<5) + mf*16 + ((r & 1) << 3) + a_)*2 + kh] = m;
        }
        __syncthreads();

        float alpha[4];
        #pragma unroll
        for (int r = 0; r < 4; r++) {
            int row = (qg<<5) + (r >> 1)*16 + ((r & 1) << 3) + a_;
            float tm = fmaxf(red[row*2], red[row*2 + 1]);
            float mn = fmaxf(m_run[r], tm);
            alpha[r] = fexp2(m_run[r] - mn);
            m_run[r] = mn;
            if (kh == 0 && b_ == 0) al_s[row] = alpha[r];
        }
        float psum[4] = {0.f, 0.f, 0.f, 0.f};
        #pragma unroll
        for (int mf = 0; mf < 2; mf++)
            #pragma unroll
            for (int c2 = 0; c2 < 2; c2++) {
                int row = (qg<<5) + mf*16 + (c2 << 3) + a_;
                float mrow = m_run[mf*2 + c2];
                #pragma unroll
                for (int nf = 0; nf < 2; nf++)
                    #pragma unroll
                    for (int c1 = 0; c1 < 2; c1++) {
                        float p = fexp2(s[mf][nf][c2*2 + c1] - mrow);
                        psum[mf*2 + c2] += p;
                        Ps[((kh<<4) + nf*8 + 2*b_ + c1)*136 + row] = p;
                    }
            }
        #pragma unroll
        for (int r = 0; r < 4; r++) {
            float ps = psum[r];
            ps += __shfl_xor_sync(0xffffffffu, ps, 1);
            ps += __shfl_xor_sync(0xffffffffu, ps, 2);
            if (b_ == 0)
                red2[((qg<<5) + (r >> 1)*16 + ((r & 1) << 3) + a_)*2 + kh] = ps;
        }
        __syncthreads();

        #pragma unroll
        for (int r = 0; r < 4; r++) {
            int row = (qg<<5) + (r >> 1)*16 + ((r & 1) << 3) + a_;
            l_run[r] = l_run[r]*alpha[r] + red2[row*2] + red2[row*2 + 1];
        }
        #pragma unroll
        for (int mf8 = 0; mf8 < 8; mf8++) {
            float al0 = al_s[mf8*16 + a_];
            float al1 = al_s[mf8*16 + 8 + a_];
            #pragma unroll
            for (int nd = 0; nd < 3; nd++) {
                o_acc[mf8][nd][0] *= al0; o_acc[mf8][nd][1] *= al0;
                o_acc[mf8][nd][2] *= al1; o_acc[mf8][nd][3] *= al1;
            }
        }

        #pragma unroll
        for (int kf = 0; kf < 4; kf++) {
            unsigned Bv[3][2];
            #pragma unroll
            for (int nd = 0; nd < 3; nd++) {
                const float* vp = Vsb + (db + nd*8 + a_)*36 + b_;
                Bv[nd][0] = __float_as_uint(vp[kf*8]);
                Bv[nd][1] = __float_as_uint(vp[kf*8 + 4]);
            }
            #pragma unroll
            for (int mf8 = 0; mf8 < 8; mf8++) {
                unsigned A4[4];
                A4[0] = __float_as_uint(pP[kf*1088 + mf8*16]);
                A4[1] = __float_as_uint(pP[kf*1088 + mf8*16 + 8]);
                A4[2] = __float_as_uint(pP[kf*1088 + mf8*16 + 544]);
                A4[3] = __float_as_uint(pP[kf*1088 + mf8*16 + 552]);
                mma8(o_acc[mf8][0], A4, Bv[0][0], Bv[0][1]);
                mma8(o_acc[mf8][1], A4, Bv[1][0], Bv[1][1]);
                mma8(o_acc[mf8][2], A4, Bv[2][0], Bv[2][1]);
            }
        }
        __syncthreads();
        if (t + 2 < 64) FKV(t + 2, bi);
        cpac();
    }

    if (kh == 0 && b_ == 0) {
        #pragma unroll
        for (int r = 0; r < 4; r++)
            al_s[(qg<<5) + (r >> 1)*16 + ((r & 1) << 3) + a_] = 1.f / l_run[r];
    }
    __syncthreads();
    #pragma unroll
    for (int mf8 = 0; mf8 < 8; mf8++) {
        float i0 = al_s[mf8*16 + a_];
        float i1 = al_s[mf8*16 + 8 + a_];
        #pragma unroll
        for (int nd = 0; nd < 3; nd++) {
            int d0 = db + nd*8 + 2*b_;
            long long r0 = (long long)d0*NP + n0 + mf8*16 + a_;
            Ob[r0]          = f2tff(o_acc[mf8][nd][0] * i0);
            Ob[r0 + NP]     = f2tff(o_acc[mf8][nd][1] * i0);
            Ob[r0 + 8]      = f2tff(o_acc[mf8][nd][2] * i1);
            Ob[r0 + NP + 8] = f2tff(o_acc[mf8][nd][3] * i1);
        }
    }
}

// ---------------- kNN gather + VN-leaky + mean pool ----------------
__global__ __launch_bounds__(128) void gather_leaky(const float* __restrict__ G,
                                                    const int* __restrict__ knn,
                                                    float* __restrict__ X5)
{
    int bn = blockIdx.x;
    int b = bn >> 11, n = bn & 2047;
    int o = threadIdx.x;
    __shared__ int ridx[8];
    if (o < 8) ridx[o] = knn[((b*8 + o) << 11) + n];
    __syncthreads();
    const float* gc = G + (long long)bn*1536;
    float pc0 = gc[128 + o],        dc0 = gc[384 + o];
    float pc1 = gc[512 + 128 + o],  dc1 = gc[512 + 384 + o];
    float pc2 = gc[1024 + 128 + o], dc2 = gc[1024 + 384 + o];
    float a0 = 0.f, a1 = 0.f, a2 = 0.f;
    #pragma unroll
    for (int k = 0; k < 8; k++) {
        const float* gr = G + (long long)ridx[k]*1536;
        float p0 = gr[o] + pc0;
        float p1 = gr[512 + o] + pc1;
        float p2 = gr[1024 + o] + pc2;
        float d0 = gr[256 + o] + dc0;
        float d1 = gr[512 + 256 + o] + dc1;
        float d2 = gr[1024 + 256 + o] + dc2;
        float dot = p0*d0 + p1*d1 + p2*d2;
        if (dot < 0.f) {
            float f = 0.8f * dot / (d0*d0 + d1*d1 + d2*d2 + 1e-6f);
            p0 -= f*d0; p1 -= f*d1; p2 -= f*d2;
        }
        a0 += p0; a1 += p1; a2 += p2;
    }
    float* y = X5 + (long long)b*(2*NC*M3) + (long long)(128 + o)*M3 + n;
    y[0] = f2tff(a0*0.125f); y[2048] = f2tff(a1*0.125f); y[4096] = f2tff(a2*0.125f);
}

// ---------------- elementwise VN-leaky ----------------
__global__ void leaky_ew(const float* __restrict__ P, const float* __restrict__ D,
                         float* __restrict__ Y)
{
    int idx = blockIdx.x*256 + threadIdx.x;
    int n = idx & 2047;
    int bo = idx >> 11;
    long long base = ((long long)bo*3 << 11) + n;
    float p0 = P[base], p1 = P[base + 2048], p2 = P[base + 4096];
    float d0 = D[base], d1 = D[base + 2048], d2 = D[base + 4096];
    float dot = p0*d0 + p1*d1 + p2*d2;
    if (dot < 0.f) {
        float f = 0.8f * dot / (d0*d0 + d1*d1 + d2*d2 + 1e-6f);
        p0 -= f*d0; p1 -= f*d1; p2 -= f*d2;
    }
    Y[base] = f2tff(p0); Y[base + 2048] = f2tff(p1); Y[base + 4096] = f2tff(p2);
}

// ---------------- conv4 leaky + residual + output transpose ----------------
__global__ void final_k(const float* __restrict__ P, const float* __restrict__ D,
                        const float* __restrict__ vnx, float* __restrict__ out)
{
    int idx = blockIdx.x*256 + threadIdx.x;
    int n = idx & 2047;
    int o = (idx >> 11) & 127;
    int b = idx >> 18;
    long long base2 = (((long long)(b*NC + o))*3 << 11) + n;
    float p0 = P[base2], p1 = P[base2 + 2048], p2 = P[base2 + 4096];
    float d0 = D[base2], d1 = D[base2 + 2048], d2 = D[base2 + 4096];
    float dot = p0*d0 + p1*d1 + p2*d2;
    if (dot < 0.f) {
        float f = 0.8f * dot / (d0*d0 + d1*d1 + d2*d2 + 1e-6f);
        p0 -= f*d0; p1 -= f*d1; p2 -= f*d2;
    }
    float r0 = vnx[base2], r1 = vnx[base2 + 2048], r2 = vnx[base2 + 4096];
    float* q = out + ((long long)(b*NP + n))*ND + 3*o;
    q[0] = r0 + p0; q[1] = r1 + p1; q[2] = r2 + p2;
}

// ---------------- host ----------------
extern "C" void kernel_launch(void* const* d_in, const int* in_sizes, int n_in,
                              void* d_out, int out_size)
{
    (void)in_sizes; (void)n_in; (void)out_size;
    const float* x  = (const float*)d_in[0];
    const int* knn  = (const int*)d_in[1];
    const float* g1 = (const float*)d_in[2];
    const float* b1 = (const float*)d_in[3];
    const float* g2 = (const float*)d_in[4];
    const float* b2 = (const float*)d_in[5];
    const float* Wq = (const float*)d_in[6];
    const float* Wk = (const float*)d_in[7];
    const float* Wv = (const float*)d_in[8];
    const float* Wo = (const float*)d_in[9];
    const float* W1 = (const float*)d_in[10];
    const float* U1 = (const float*)d_in[11];
    const float* W2 = (const float*)d_in[12];
    const float* W3 = (const float*)d_in[13];
    const float* U3 = (const float*)d_in[14];
    const float* W4 = (const float*)d_in[15];
    const float* U4 = (const float*)d_in[16];
    float* out = (float*)d_out;

    float *normx,*qkv,*ao,*G,*x5,*vnx,*nx2,*p3,*d3,*h,*p4,*d4,*cw,*wr;
    cudaGetSymbolAddress((void**)&normx, g_normx);
    cudaGetSymbolAddress((void**)&qkv, g_qkv);
    cudaGetSymbolAddress((void**)&ao, g_ao);
    cudaGetSymbolAddress((void**)&G,  g_G);
    cudaGetSymbolAddress((void**)&x5, g_x5);
    cudaGetSymbolAddress((void**)&vnx, g_vnx);
    cudaGetSymbolAddress((void**)&nx2, g_nx2);
    cudaGetSymbolAddress((void**)&p3, g_p3);
    cudaGetSymbolAddress((void**)&d3, g_d3);
    cudaGetSymbolAddress((void**)&h,  g_h);
    cudaGetSymbolAddress((void**)&p4, g_p4);
    cudaGetSymbolAddress((void**)&d4, g_d4);
    cudaGetSymbolAddress((void**)&cw, g_cw);
    cudaGetSymbolAddress((void**)&wr, g_wr);

    cudaFuncSetAttribute(flash_tc, cudaFuncAttributeMaxDynamicSharedMemorySize, FTC_SMEM);
    cudaFuncSetAttribute(gemm_k, cudaFuncAttributeMaxDynamicSharedMemorySize, GSMEM);

    prep_w<<<1408, 256>>>(Wq, Wk, Wv, Wo, W2, W3, U3, W4, U4, wr);
    prep_cw<<<256, 256>>>(W1, U1, cw);
    ln_k<<<NB*NP, 128>>>(x, g1, b1, normx, 0);

    long long sN = (long long)NC*M3;
    long long sQ = (long long)ND*M3;
    long long sX5 = (long long)2*NC*M3;
    const float qsc = 0.125f * 1.44269504088896f;

    // fused QKV
    gemm_k<<<dim3(48,9,NB), 256, GSMEM>>>(wr, nullptr, normx, qkv, nullptr, nullptr,
                                          128, M3, sN, 0, sQ, 0, M3, 1, 2, 2, qsc, 0);

    flash_tc<<<dim3(16, NH, NB), 256, FTC_SMEM>>>(qkv, qkv + QOFF, qkv + 2*QOFF, ao);

    gemm_k<<<dim3(48,1,NB), 256, GSMEM>>>(wr + 147456, nullptr, ao, x5, nullptr, nullptr,
                                          384, M3, sQ, 0, sX5, 0, M3, 1, 0, 2, 1.0f, 0);

    gemm_k<<<dim3(16,4,12), 256, GSMEM>>>(cw, nullptr, normx, G, nullptr, nullptr,
                                          128, M3, sN, 2048, (long long)NP*1536, 512, 1, 1536, 1, 0, 1.0f, 0);
    gather_leaky<<<NB*NP, 128>>>(G, knn, x5);

    gemm_k<<<dim3(48,1,NB), 256, GSMEM>>>(wr + 196608, nullptr, x5, vnx, nullptr, x,
                                          256, M3, sX5, 0, sN, 0, M3, 1, 0, 1, 1.0f, 0);

    ln_k<<<NB*NP, 128>>>(vnx, g2, b2, nx2, 1);

    // fused W3 + U3
    gemm_k<<<dim3(48,4,NB), 256, GSMEM>>>(wr + 229376, wr + 262144, nx2, p3, d3, nullptr,
                                          128, M3, sN, 0, sX5, 0, M3, 1, 0, 0, 1.0f, 2);
    leaky_ew<<<NB*2*NC*NP/256, 256>>>(p3, d3, h);

    // fused W4 + U4
    gemm_k<<<dim3(48,2,NB), 256, GSMEM>>>(wr + 294912, wr + 327680, h, p4, d4, nullptr,
                                          256, M3, sX5, 0, sN, 0, M3, 1, 0, 0, 1.0f, 1);

    final_k<<<NB*NC*NP/256, 256>>>(p4, d4, vnx, out);
}

// round 9
// speedup vs baseline: 1.3679x; 1.0726x over previous
#include <cuda_runtime.h>
#include <math.h>

#define NB 4
#define NP 2048
#define NC 128
#define ND 384
#define NH 6
#define FD 192
#define M3 (3*NP)
#define QOFF (NB*ND*M3)

__device__ float g_normx[NB*NC*3*NP];
__device__ float g_qkv[3*NB*ND*3*NP];
__device__ float g_ao[NB*ND*3*NP];
__device__ float g_G [NB*NP*1536];
__device__ float g_x5[NB*2*NC*3*NP];
__device__ float g_vnx[NB*NC*3*NP];
__device__ float g_nx2[NB*NC*3*NP];
__device__ float g_p3[NB*2*NC*3*NP];
__device__ float g_d3[NB*2*NC*3*NP];
__device__ float g_h [NB*2*NC*3*NP];
__device__ float g_p4[NB*NC*3*NP];
__device__ float g_d4[NB*NC*3*NP];
__device__ float g_cw[512*128];
__device__ float g_wr[360448];

__device__ __forceinline__ unsigned f2tf(float f) {
    unsigned u;
    asm("cvt.rna.tf32.f32 %0, %1;" : "=r"(u) : "f"(f));
    return u;
}
__device__ __forceinline__ float f2tff(float f) { return __uint_as_float(f2tf(f)); }
__device__ __forceinline__ float fexp2(float x) {
    float r;
    asm("ex2.approx.f32 %0, %1;" : "=f"(r) : "f"(x));
    return r;
}
__device__ __forceinline__ void mma8(float* d, const unsigned* a, unsigned b0, unsigned b1) {
    asm volatile("mma.sync.aligned.m16n8k8.row.col.f32.tf32.tf32.f32 "
                 "{%0,%1,%2,%3},{%4,%5,%6,%7},{%8,%9},{%0,%1,%2,%3};"
                 : "+f"(d[0]), "+f"(d[1]), "+f"(d[2]), "+f"(d[3])
                 : "r"(a[0]), "r"(a[1]), "r"(a[2]), "r"(a[3]), "r"(b0), "r"(b1));
}
__device__ __forceinline__ void cpa16(unsigned dst, const void* src) {
    asm volatile("cp.async.cg.shared.global [%0], [%1], 16;" :: "r"(dst), "l"(src));
}
__device__ __forceinline__ void cpac() { asm volatile("cp.async.commit_group;"); }
__device__ __forceinline__ void cpaw1() { asm volatile("cp.async.wait_group 1;"); }
__device__ __forceinline__ void cpaw2() { asm volatile("cp.async.wait_group 2;"); }

// ---------------- weight prep ----------------
__global__ void prep_w(const float* __restrict__ Wq, const float* __restrict__ Wk,
                       const float* __restrict__ Wv, const float* __restrict__ Wo,
                       const float* __restrict__ W2, const float* __restrict__ W3,
                       const float* __restrict__ U3, const float* __restrict__ W4,
                       const float* __restrict__ U4, float* __restrict__ wr)
{
    int i = blockIdx.x*256 + threadIdx.x;
    if (i >= 360448) return;
    float v;
    if      (i < 49152)  v = Wq[i];
    else if (i < 98304)  v = Wk[i - 49152];
    else if (i < 147456) v = Wv[i - 98304];
    else if (i < 196608) v = Wo[i - 147456];
    else if (i < 229376) v = W2[i - 196608];
    else if (i < 262144) v = W3[i - 229376];
    else if (i < 294912) v = U3[i - 262144];
    else if (i < 327680) v = W4[i - 294912];
    else                 v = U4[i - 327680];
    wr[i] = f2tff(v);
}

__global__ void prep_cw(const float* __restrict__ W1, const float* __restrict__ U1,
                        float* __restrict__ CW)
{
    int idx = blockIdx.x * 256 + threadIdx.x;
    if (idx >= 512*128) return;
    int col = idx >> 7, c = idx & 127;
    int a = col / 128, o = col % 128;
    float v;
    if      (a == 0) v = W1[o*256 + c];
    else if (a == 1) v = W1[o*256 + 128 + c] - W1[o*256 + c];
    else if (a == 2) v = U1[o*256 + c];
    else             v = U1[o*256 + 128 + c] - U1[o*256 + c];
    CW[col*128 + c] = f2tff(v);
}

// ---------------- vector-norm layernorm ----------------
__global__ __launch_bounds__(128) void ln_k(const float* __restrict__ in,
                                            const float* __restrict__ g,
                                            const float* __restrict__ bb,
                                            float* __restrict__ out, int mode)
{
    int bn = blockIdx.x;
    int b = bn >> 11, n = bn & 2047;
    int c = threadIdx.x;
    float v0, v1, v2;
    if (mode == 0) {
        const float* p = in + (long long)bn*384 + 3*c;
        v0 = p[0]; v1 = p[1]; v2 = p[2];
    } else {
        const float* p = in + ((long long)b*NC + c)*M3 + n;
        v0 = p[0]; v1 = p[2048]; v2 = p[4096];
    }
    float nrm = sqrtf(v0*v0 + v1*v1 + v2*v2 + 1e-6f);
    float s = nrm, s2 = nrm*nrm;
    for (int m = 16; m; m >>= 1) {
        s  += __shfl_xor_sync(0xffffffffu, s,  m);
        s2 += __shfl_xor_sync(0xffffffffu, s2, m);
    }
    __shared__ float sb[8];
    int w = c >> 5, lane = c & 31;
    if (!lane) { sb[w] = s; sb[4 + w] = s2; }
    __syncthreads();
    float ts  = sb[0] + sb[1] + sb[2] + sb[3];
    float ts2 = sb[4] + sb[5] + sb[6] + sb[7];
    float mu  = ts * (1.f/128.f);
    float var = ts2 * (1.f/128.f) - mu*mu;
    float nhat = (nrm - mu) / sqrtf(var + 1e-5f);
    float scale = (g[c]*nhat + bb[c]) / nrm;
    float* q = out + ((long long)b*NC + c)*M3 + n;
    q[0] = f2tff(v0*scale); q[2048] = f2tff(v1*scale); q[4096] = f2tff(v2*scale);
}

// ---------------- GEMM v4 (unchanged from R8) ----------------
#define GSMEM (26880*4)
__global__ __launch_bounds__(256, 2) void gemm_k(
    const float* __restrict__ W, const float* __restrict__ Wb,
    const float* __restrict__ X, float* __restrict__ Y, float* __restrict__ Y2,
    const float* __restrict__ Res,
    int Cin, int ldx,
    long long xsb, long long xsi, long long ysb, long long ysi,
    int oso, int osm, int zflag, int mode, float oscale, int ysplit)
{
    extern __shared__ float smn[];
    int z = blockIdx.z;
    int b  = (zflag == 1) ? z/3 : z;
    int i3 = (zflag == 1) ? z%3 : 0;
    const float* xb = X + (long long)b*xsb + (long long)i3*xsi;
    int by = blockIdx.y;
    int o0;
    float* yb;
    float osc = oscale;
    if (zflag == 2) {
        int wsel = by / 3;
        o0 = (by % 3) * 128;
        W += wsel * 49152;
        yb = Y + (long long)wsel*QOFF + (long long)b*ysb;
        if (wsel) osc = 1.0f;
    } else if (ysplit > 0 && by >= ysplit) {
        o0 = (by - ysplit) * 128;
        W = Wb;
        yb = Y2 + (long long)b*ysb + (long long)i3*ysi;
    } else {
        o0 = by * 128;
        yb = Y + (long long)b*ysb + (long long)i3*ysi;
    }
    int m0 = blockIdx.x * 128;
    int tid = threadIdx.x;
    int wid = tid >> 5, lane = tid & 31;
    int a_ = lane >> 2, b_ = lane & 3;
    int wy = wid >> 1, wx = wid & 1;
    unsigned sm_u = (unsigned)__cvta_generic_to_shared(smn);

    float acc[2][8][4];
    #pragma unroll
    for (int i = 0; i < 2; i++)
        #pragma unroll
        for (int j = 0; j < 8; j++)
            #pragma unroll
            for (int c = 0; c < 4; c++) acc[i][j][c] = 0.f;

    int nchunk = Cin >> 5;
    int fo = tid >> 3, fk4 = (tid & 7) << 2;
    int fr = tid >> 5, fc4 = (tid & 31) << 2;

    #define GFILL(ch) do { \
        int k0 = (ch) << 5; \
        int stg = (ch) % 3; \
        unsigned swu = sm_u + (unsigned)(stg*8960*4); \
        unsigned sxu = swu + (unsigned)(4608*4); \
        cpa16(swu + (unsigned)((fo*36 + fk4)*4),        W + (long long)(o0 + fo)*Cin + k0 + fk4); \
        cpa16(swu + (unsigned)(((fo+32)*36 + fk4)*4),   W + (long long)(o0 + fo + 32)*Cin + k0 + fk4); \
        cpa16(swu + (unsigned)(((fo+64)*36 + fk4)*4),   W + (long long)(o0 + fo + 64)*Cin + k0 + fk4); \
        cpa16(swu + (unsigned)(((fo+96)*36 + fk4)*4),   W + (long long)(o0 + fo + 96)*Cin + k0 + fk4); \
        cpa16(sxu + (unsigned)((fr*136 + fc4)*4),       xb + (long long)(k0 + fr)*ldx + m0 + fc4); \
        cpa16(sxu + (unsigned)(((fr+8)*136 + fc4)*4),   xb + (long long)(k0 + fr + 8)*ldx + m0 + fc4); \
        cpa16(sxu + (unsigned)(((fr+16)*136 + fc4)*4),  xb + (long long)(k0 + fr + 16)*ldx + m0 + fc4); \
        cpa16(sxu + (unsigned)(((fr+24)*136 + fc4)*4),  xb + (long long)(k0 + fr + 24)*ldx + m0 + fc4); \
    } while (0)

    GFILL(0); cpac();
    if (nchunk > 1) GFILL(1);
    cpac();

    for (int ch = 0; ch < nchunk; ch++) {
        cpaw1();
        __syncthreads();
        int stg = ch % 3;
        const float* swb = smn + stg*8960;
        const float* sxb = swb + 4608;
        const float* pA0 = swb + (wy*32 + a_)*36 + b_;
        const float* pA1 = pA0 + 576;
        const float* pX  = sxb + b_*136 + wx*64 + a_;
        #pragma unroll
        for (int kf = 0; kf < 4; kf++) {
            unsigned A[2][4];
            A[0][0] = __float_as_uint(pA0[kf*8]);
            A[0][1] = __float_as_uint(pA0[kf*8 + 288]);
            A[0][2] = __float_as_uint(pA0[kf*8 + 4]);
            A[0][3] = __float_as_uint(pA0[kf*8 + 292]);
            A[1][0] = __float_as_uint(pA1[kf*8]);
            A[1][1] = __float_as_uint(pA1[kf*8 + 288]);
            A[1][2] = __float_as_uint(pA1[kf*8 + 4]);
            A[1][3] = __float_as_uint(pA1[kf*8 + 292]);
            #pragma unroll
            for (int nf = 0; nf < 8; nf++) {
                unsigned B0 = __float_as_uint(pX[kf*1088 + nf*8]);
                unsigned B1 = __float_as_uint(pX[kf*1088 + nf*8 + 544]);
                mma8(acc[0][nf], A[0], B0, B1);
                mma8(acc[1][nf], A[1], B0, B1);
            }
        }
        if (ch + 2 < nchunk) GFILL(ch + 2);
        cpac();
    }

    int ob = o0 + wy*32, mb = m0 + wx*64;
    if (osm == 1) {
        #pragma unroll
        for (int mf = 0; mf < 2; mf++)
            #pragma unroll
            for (int nf = 0; nf < 8; nf++) {
                int o = ob + mf*16 + a_;
                int m = mb + nf*8 + 2*b_;
                float2 v0 = make_float2(acc[mf][nf][0], acc[mf][nf][1]);
                float2 v1 = make_float2(acc[mf][nf][2], acc[mf][nf][3]);
                if (mode & 1) {
                    long long rb = (long long)b*NP*ND;
                    v0.x += Res[rb + (long long)(m & 2047)*ND + 3*o + (m >> 11)];
                    v0.y += Res[rb + (long long)((m+1) & 2047)*ND + 3*o + ((m+1) >> 11)];
                    v1.x += Res[rb + (long long)(m & 2047)*ND + 3*(o+8) + (m >> 11)];
                    v1.y += Res[rb + (long long)((m+1) & 2047)*ND + 3*(o+8) + ((m+1) >> 11)];
                }
                if (mode & 2) {
                    v0.x = f2tff(v0.x*osc); v0.y = f2tff(v0.y*osc);
                    v1.x = f2tff(v1.x*osc); v1.y = f2tff(v1.y*osc);
                }
                *(float2*)(yb + (long long)o*oso + m) = v0;
                *(float2*)(yb + (long long)(o+8)*oso + m) = v1;
            }
    } else {
        #pragma unroll
        for (int mf = 0; mf < 2; mf++)
            #pragma unroll
            for (int nf = 0; nf < 8; nf++)
                #pragma unroll
                for (int c = 0; c < 4; c++) {
                    int o = ob + mf*16 + a_ + ((c >> 1) ? 8 : 0);
                    int m = mb + nf*8 + 2*b_ + (c & 1);
                    yb[(long long)o*oso + (long long)m*osm] = acc[mf][nf][c];
                }
    }
}

// ---------------- flash v5: Q-in-registers, d-split warps ----------------
// smem (floats): Sx 0..8192 | Ps 8192..12544 | (Q staging 0..24576 prologue only)
//                K 24576..36864 (2x6144 swz) | V 36864..50688 (2x6912) | al 50688..50816
#define SXF 0
#define PSF 8192
#define KSF 24576
#define VSF 36864
#define ALF 50688
#define FTC_SMEM (50816*4)

__global__ __launch_bounds__(256, 1) void flash_tc(const float* __restrict__ Q,
                                                   const float* __restrict__ K,
                                                   const float* __restrict__ V,
                                                   float* __restrict__ O)
{
    extern __shared__ float sm[];
    float* Ps   = sm + PSF;
    float* al_s = sm + ALF;
    unsigned sm_u = (unsigned)__cvta_generic_to_shared(sm);

    int n0 = blockIdx.x * 128;
    long long hb = (long long)(blockIdx.z*NH + blockIdx.y) * FD * NP;
    const float* Qb = Q + hb;
    const float* Kb = K + hb;
    const float* Vb = V + hb;
    float* Ob = O + hb;

    int tid = threadIdx.x;
    int wid = tid >> 5, lane = tid & 31;
    int a_ = lane >> 2, b_ = lane & 3;
    int qg = wid >> 1, dh = wid & 1;

    int fd8 = tid >> 3, ft4 = (tid & 7) << 2;
    #define FKV(t, bi) do { \
        int kt = (t) << 5; \
        unsigned ku = sm_u + (unsigned)((KSF + (bi)*6144)*4); \
        unsigned vu = sm_u + (unsigned)((VSF + (bi)*6912)*4); \
        _Pragma("unroll") \
        for (int i = 0; i < 6; i++) { \
            int d = fd8 + i*32; \
            cpa16(ku + (unsigned)(((d << 5) + (ft4 ^ ((d & 3) << 3)))*4), Kb + (long long)d*NP + kt + ft4); \
            cpa16(vu + (unsigned)((d*36 + ft4)*4),                        Vb + (long long)d*NP + kt + ft4); \
        } \
    } while (0)

    // prologue: Q staging (swizzled [192][128]) + KV(0) + KV(1)
    {
        int qd = tid >> 5, qc4 = (tid & 31) << 2;
        #pragma unroll
        for (int i = 0; i < 24; i++) {
            int d = qd + i*8;
            cpa16(sm_u + (unsigned)(((d << 7) + (qc4 ^ ((d & 3) << 3)))*4),
                  Qb + (long long)d*NP + n0 + qc4);
        }
    }
    cpac();
    FKV(0, 0); cpac();
    FKV(1, 1); cpac();

    cpaw2();
    __syncthreads();

    // extract Q fragments for this warp (32q x 96d) into registers
    unsigned qreg[12][2][4];
    {
        int s8 = b_ << 3;
        int qv00 = ((qg<<5) + a_) ^ s8;
        int qv01 = ((qg<<5) + 8 + a_) ^ s8;
        int qv10 = ((qg<<5) + 16 + a_) ^ s8;
        int qv11 = ((qg<<5) + 24 + a_) ^ s8;
        const float* pQ = sm + (b_ << 7);
        #pragma unroll
        for (int kf = 0; kf < 12; kf++) {
            int qb2 = (dh*12 + kf) << 10;
            qreg[kf][0][0] = __float_as_uint(pQ[qb2 + qv00]);
            qreg[kf][0][1] = __float_as_uint(pQ[qb2 + qv01]);
            qreg[kf][0][2] = __float_as_uint(pQ[qb2 + 512 + qv00]);
            qreg[kf][0][3] = __float_as_uint(pQ[qb2 + 512 + qv01]);
            qreg[kf][1][0] = __float_as_uint(pQ[qb2 + qv10]);
            qreg[kf][1][1] = __float_as_uint(pQ[qb2 + qv11]);
            qreg[kf][1][2] = __float_as_uint(pQ[qb2 + 512 + qv10]);
            qreg[kf][1][3] = __float_as_uint(pQ[qb2 + 512 + qv11]);
        }
    }

    int tv[4];
    {
        int s8 = b_ << 3;
        #pragma unroll
        for (int n = 0; n < 4; n++) tv[n] = ((n << 3) + a_) ^ s8;
    }

    float m_run[2] = {-1e30f, -1e30f};
    float l_run[2] = {0.f, 0.f};
    float o_acc[2][12][4];
    #pragma unroll
    for (int i = 0; i < 2; i++)
        #pragma unroll
        for (int j = 0; j < 12; j++)
            #pragma unroll
            for (int c = 0; c < 4; c++) o_acc[i][j][c] = 0.f;

    int rA = (qg<<5) + (dh<<4) + a_;
    int fbase = ((qg*2 + dh)*2) << 2;   // frag_idx base for writes: (qg,dh,mf)*4
    int rb0 = ((qg*2 + 0)*2 + dh) << 2; // read base dh'=0, mf=dh
    int rb1 = ((qg*2 + 1)*2 + dh) << 2; // read base dh'=1

    for (int t = 0; t < 64; t++) {
        cpaw1();
        __syncthreads();
        int bi = t & 1;
        const float* Ksb = sm + KSF + bi*6144;
        const float* Vsb = sm + VSF + bi*6912;
        const float* pK = Ksb + dh*3072 + (b_ << 5);

        // ---- QK in two 16-key passes ----
        #pragma unroll
        for (int nfh = 0; nfh < 2; nfh++) {
            float s16[2][2][4];
            #pragma unroll
            for (int mf = 0; mf < 2; mf++)
                #pragma unroll
                for (int nf = 0; nf < 2; nf++)
                    #pragma unroll
                    for (int c = 0; c < 4; c++) s16[mf][nf][c] = 0.f;
            #pragma unroll
            for (int kf = 0; kf < 12; kf++) {
                int kb = kf << 8;
                unsigned B00 = __float_as_uint(pK[kb + tv[nfh*2]]);
                unsigned B01 = __float_as_uint(pK[kb + 128 + tv[nfh*2]]);
                unsigned B10 = __float_as_uint(pK[kb + tv[nfh*2+1]]);
                unsigned B11 = __float_as_uint(pK[kb + 128 + tv[nfh*2+1]]);
                mma8(s16[0][0], qreg[kf][0], B00, B01);
                mma8(s16[1][0], qreg[kf][1], B00, B01);
                mma8(s16[0][1], qreg[kf][0], B10, B11);
                mma8(s16[1][1], qreg[kf][1], B10, B11);
            }
            #pragma unroll
            for (int mf = 0; mf < 2; mf++)
                #pragma unroll
                for (int nf = 0; nf < 2; nf++) {
                    int fi = (fbase + (mf << 2)) + nfh*2 + nf;
                    *(float4*)(sm + SXF + fi*128 + (lane << 2)) =
                        make_float4(s16[mf][nf][0], s16[mf][nf][1],
                                    s16[mf][nf][2], s16[mf][nf][3]);
                }
        }
        __syncthreads();

        // ---- softmax: this warp owns rows rA, rA+8 (16 rows of qg, mf=dh) ----
        {
            float st[4][4];
            #pragma unroll
            for (int nfg = 0; nfg < 4; nfg++) {
                float4 xa = *(const float4*)(sm + SXF + (rb0 + nfg)*128 + (lane << 2));
                float4 xb2 = *(const float4*)(sm + SXF + (rb1 + nfg)*128 + (lane << 2));
                st[nfg][0] = xa.x + xb2.x; st[nfg][1] = xa.y + xb2.y;
                st[nfg][2] = xa.z + xb2.z; st[nfg][3] = xa.w + xb2.w;
            }
            float mA = -1e30f, mB = -1e30f;
            #pragma unroll
            for (int nfg = 0; nfg < 4; nfg++) {
                mA = fmaxf(mA, fmaxf(st[nfg][0], st[nfg][1]));
                mB = fmaxf(mB, fmaxf(st[nfg][2], st[nfg][3]));
            }
            mA = fmaxf(mA, __shfl_xor_sync(0xffffffffu, mA, 1));
            mA = fmaxf(mA, __shfl_xor_sync(0xffffffffu, mA, 2));
            mB = fmaxf(mB, __shfl_xor_sync(0xffffffffu, mB, 1));
            mB = fmaxf(mB, __shfl_xor_sync(0xffffffffu, mB, 2));
            float mnA = fmaxf(m_run[0], mA);
            float mnB = fmaxf(m_run[1], mB);
            float alA = fexp2(m_run[0] - mnA);
            float alB = fexp2(m_run[1] - mnB);
            m_run[0] = mnA; m_run[1] = mnB;
            float psA = 0.f, psB = 0.f;
            #pragma unroll
            for (int nfg = 0; nfg < 4; nfg++) {
                int kcol = (nfg << 3) + (b_ << 1);
                #pragma unroll
                for (int c1 = 0; c1 < 2; c1++) {
                    float pA = fexp2(st[nfg][c1] - mnA);
                    float pB = fexp2(st[nfg][2 + c1] - mnB);
                    psA += pA; psB += pB;
                    Ps[(kcol + c1)*136 + rA] = pA;
                    Ps[(kcol + c1)*136 + rA + 8] = pB;
                }
            }
            psA += __shfl_xor_sync(0xffffffffu, psA, 1);
            psA += __shfl_xor_sync(0xffffffffu, psA, 2);
            psB += __shfl_xor_sync(0xffffffffu, psB, 1);
            psB += __shfl_xor_sync(0xffffffffu, psB, 2);
            l_run[0] = l_run[0]*alA + psA;
            l_run[1] = l_run[1]*alB + psB;
            if (b_ == 0) { al_s[rA] = alA; al_s[rA + 8] = alB; }
        }
        __syncthreads();

        // ---- rescale + PV (warp: 32q of qg x 96d of dh) ----
        {
            float al0 = al_s[(qg<<5) + a_];
            float al1 = al_s[(qg<<5) + 8 + a_];
            float al2 = al_s[(qg<<5) + 16 + a_];
            float al3 = al_s[(qg<<5) + 24 + a_];
            #pragma unroll
            for (int nd = 0; nd < 12; nd++) {
                o_acc[0][nd][0] *= al0; o_acc[0][nd][1] *= al0;
                o_acc[0][nd][2] *= al1; o_acc[0][nd][3] *= al1;
                o_acc[1][nd][0] *= al2; o_acc[1][nd][1] *= al2;
                o_acc[1][nd][2] *= al3; o_acc[1][nd][3] *= al3;
            }
            const float* pP = Ps + b_*136 + (qg<<5) + a_;
            const float* pV = Vsb + (dh*96 + a_)*36 + b_;
            #pragma unroll
            for (int kf = 0; kf < 4; kf++) {
                unsigned A40[4], A41[4];
                A40[0] = __float_as_uint(pP[kf*1088]);
                A40[1] = __float_as_uint(pP[kf*1088 + 8]);
                A40[2] = __float_as_uint(pP[kf*1088 + 544]);
                A40[3] = __float_as_uint(pP[kf*1088 + 552]);
                A41[0] = __float_as_uint(pP[kf*1088 + 16]);
                A41[1] = __float_as_uint(pP[kf*1088 + 24]);
                A41[2] = __float_as_uint(pP[kf*1088 + 560]);
                A41[3] = __float_as_uint(pP[kf*1088 + 568]);
                #pragma unroll
                for (int nd = 0; nd < 12; nd++) {
                    unsigned Bv0 = __float_as_uint(pV[nd*288 + kf*8]);
                    unsigned Bv1 = __float_as_uint(pV[nd*288 + kf*8 + 4]);
                    mma8(o_acc[0][nd], A40, Bv0, Bv1);
                    mma8(o_acc[1][nd], A41, Bv0, Bv1);
                }
            }
        }
        __syncthreads();
        if (t + 2 < 64) FKV(t + 2, bi);
        cpac();
    }

    if (b_ == 0) {
        al_s[rA] = 1.f / l_run[0];
        al_s[rA + 8] = 1.f / l_run[1];
    }
    __syncthreads();
    {
        float i0 = al_s[(qg<<5) + a_];
        float i1 = al_s[(qg<<5) + 8 + a_];
        float i2 = al_s[(qg<<5) + 16 + a_];
        float i3 = al_s[(qg<<5) + 24 + a_];
        #pragma unroll
        for (int nd = 0; nd < 12; nd++) {
            int d0 = dh*96 + nd*8 + 2*b_;
            long long r0 = (long long)d0*NP + n0 + (qg<<5) + a_;
            Ob[r0]           = f2tff(o_acc[0][nd][0] * i0);
            Ob[r0 + NP]      = f2tff(o_acc[0][nd][1] * i0);
            Ob[r0 + 8]       = f2tff(o_acc[0][nd][2] * i1);
            Ob[r0 + NP + 8]  = f2tff(o_acc[0][nd][3] * i1);
            Ob[r0 + 16]      = f2tff(o_acc[1][nd][0] * i2);
            Ob[r0 + NP + 16] = f2tff(o_acc[1][nd][1] * i2);
            Ob[r0 + 24]      = f2tff(o_acc[1][nd][2] * i3);
            Ob[r0 + NP + 24] = f2tff(o_acc[1][nd][3] * i3);
        }
    }
}

// ---------------- kNN gather + VN-leaky + mean pool ----------------
__global__ __launch_bounds__(128) void gather_leaky(const float* __restrict__ G,
                                                    const int* __restrict__ knn,
                                                    float* __restrict__ X5)
{
    int bn = blockIdx.x;
    int b = bn >> 11, n = bn & 2047;
    int o = threadIdx.x;
    __shared__ int ridx[8];
    if (o < 8) ridx[o] = knn[((b*8 + o) << 11) + n];
    __syncthreads();
    const float* gc = G + (long long)bn*1536;
    float pc0 = gc[128 + o],        dc0 = gc[384 + o];
    float pc1 = gc[512 + 128 + o],  dc1 = gc[512 + 384 + o];
    float pc2 = gc[1024 + 128 + o], dc2 = gc[1024 + 384 + o];
    float a0 = 0.f, a1 = 0.f, a2 = 0.f;
    #pragma unroll
    for (int k = 0; k < 8; k++) {
        const float* gr = G + (long long)ridx[k]*1536;
        float p0 = gr[o] + pc0;
        float p1 = gr[512 + o] + pc1;
        float p2 = gr[1024 + o] + pc2;
        float d0 = gr[256 + o] + dc0;
        float d1 = gr[512 + 256 + o] + dc1;
        float d2 = gr[1024 + 256 + o] + dc2;
        float dot = p0*d0 + p1*d1 + p2*d2;
        if (dot < 0.f) {
            float f = 0.8f * dot / (d0*d0 + d1*d1 + d2*d2 + 1e-6f);
            p0 -= f*d0; p1 -= f*d1; p2 -= f*d2;
        }
        a0 += p0; a1 += p1; a2 += p2;
    }
    float* y = X5 + (long long)b*(2*NC*M3) + (long long)(128 + o)*M3 + n;
    y[0] = f2tff(a0*0.125f); y[2048] = f2tff(a1*0.125f); y[4096] = f2tff(a2*0.125f);
}

// ---------------- elementwise VN-leaky ----------------
__global__ void leaky_ew(const float* __restrict__ P, const float* __restrict__ D,
                         float* __restrict__ Y)
{
    int idx = blockIdx.x*256 + threadIdx.x;
    int n = idx & 2047;
    int bo = idx >> 11;
    long long base = ((long long)bo*3 << 11) + n;
    float p0 = P[base], p1 = P[base + 2048], p2 = P[base + 4096];
    float d0 = D[base], d1 = D[base + 2048], d2 = D[base + 4096];
    float dot = p0*d0 + p1*d1 + p2*d2;
    if (dot < 0.f) {
        float f = 0.8f * dot / (d0*d0 + d1*d1 + d2*d2 + 1e-6f);
        p0 -= f*d0; p1 -= f*d1; p2 -= f*d2;
    }
    Y[base] = f2tff(p0); Y[base + 2048] = f2tff(p1); Y[base + 4096] = f2tff(p2);
}

// ---------------- conv4 leaky + residual + output transpose ----------------
__global__ void final_k(const float* __restrict__ P, const float* __restrict__ D,
                        const float* __restrict__ vnx, float* __restrict__ out)
{
    int idx = blockIdx.x*256 + threadIdx.x;
    int n = idx & 2047;
    int o = (idx >> 11) & 127;
    int b = idx >> 18;
    long long base2 = (((long long)(b*NC + o))*3 << 11) + n;
    float p0 = P[base2], p1 = P[base2 + 2048], p2 = P[base2 + 4096];
    float d0 = D[base2], d1 = D[base2 + 2048], d2 = D[base2 + 4096];
    float dot = p0*d0 + p1*d1 + p2*d2;
    if (dot < 0.f) {
        float f = 0.8f * dot / (d0*d0 + d1*d1 + d2*d2 + 1e-6f);
        p0 -= f*d0; p1 -= f*d1; p2 -= f*d2;
    }
    float r0 = vnx[base2], r1 = vnx[base2 + 2048], r2 = vnx[base2 + 4096];
    float* q = out + ((long long)(b*NP + n))*ND + 3*o;
    q[0] = r0 + p0; q[1] = r1 + p1; q[2] = r2 + p2;
}

// ---------------- host ----------------
extern "C" void kernel_launch(void* const* d_in, const int* in_sizes, int n_in,
                              void* d_out, int out_size)
{
    (void)in_sizes; (void)n_in; (void)out_size;
    const float* x  = (const float*)d_in[0];
    const int* knn  = (const int*)d_in[1];
    const float* g1 = (const float*)d_in[2];
    const float* b1 = (const float*)d_in[3];
    const float* g2 = (const float*)d_in[4];
    const float* b2 = (const float*)d_in[5];
    const float* Wq = (const float*)d_in[6];
    const float* Wk = (const float*)d_in[7];
    const float* Wv = (const float*)d_in[8];
    const float* Wo = (const float*)d_in[9];
    const float* W1 = (const float*)d_in[10];
    const float* U1 = (const float*)d_in[11];
    const float* W2 = (const float*)d_in[12];
    const float* W3 = (const float*)d_in[13];
    const float* U3 = (const float*)d_in[14];
    const float* W4 = (const float*)d_in[15];
    const float* U4 = (const float*)d_in[16];
    float* out = (float*)d_out;

    float *normx,*qkv,*ao,*G,*x5,*vnx,*nx2,*p3,*d3,*h,*p4,*d4,*cw,*wr;
    cudaGetSymbolAddress((void**)&normx, g_normx);
    cudaGetSymbolAddress((void**)&qkv, g_qkv);
    cudaGetSymbolAddress((void**)&ao, g_ao);
    cudaGetSymbolAddress((void**)&G,  g_G);
    cudaGetSymbolAddress((void**)&x5, g_x5);
    cudaGetSymbolAddress((void**)&vnx, g_vnx);
    cudaGetSymbolAddress((void**)&nx2, g_nx2);
    cudaGetSymbolAddress((void**)&p3, g_p3);
    cudaGetSymbolAddress((void**)&d3, g_d3);
    cudaGetSymbolAddress((void**)&h,  g_h);
    cudaGetSymbolAddress((void**)&p4, g_p4);
    cudaGetSymbolAddress((void**)&d4, g_d4);
    cudaGetSymbolAddress((void**)&cw, g_cw);
    cudaGetSymbolAddress((void**)&wr, g_wr);

    cudaFuncSetAttribute(flash_tc, cudaFuncAttributeMaxDynamicSharedMemorySize, FTC_SMEM);
    cudaFuncSetAttribute(gemm_k, cudaFuncAttributeMaxDynamicSharedMemorySize, GSMEM);

    prep_w<<<1408, 256>>>(Wq, Wk, Wv, Wo, W2, W3, U3, W4, U4, wr);
    prep_cw<<<256, 256>>>(W1, U1, cw);
    ln_k<<<NB*NP, 128>>>(x, g1, b1, normx, 0);

    long long sN = (long long)NC*M3;
    long long sQ = (long long)ND*M3;
    long long sX5 = (long long)2*NC*M3;
    const float qsc = 0.125f * 1.44269504088896f;

    gemm_k<<<dim3(48,9,NB), 256, GSMEM>>>(wr, nullptr, normx, qkv, nullptr, nullptr,
                                          128, M3, sN, 0, sQ, 0, M3, 1, 2, 2, qsc, 0);

    flash_tc<<<dim3(16, NH, NB), 256, FTC_SMEM>>>(qkv, qkv + QOFF, qkv + 2*QOFF, ao);

    gemm_k<<<dim3(48,1,NB), 256, GSMEM>>>(wr + 147456, nullptr, ao, x5, nullptr, nullptr,
                                          384, M3, sQ, 0, sX5, 0, M3, 1, 0, 2, 1.0f, 0);

    gemm_k<<<dim3(16,4,12), 256, GSMEM>>>(cw, nullptr, normx, G, nullptr, nullptr,
                                          128, M3, sN, 2048, (long long)NP*1536, 512, 1, 1536, 1, 0, 1.0f, 0);
    gather_leaky<<<NB*NP, 128>>>(G, knn, x5);

    gemm_k<<<dim3(48,1,NB), 256, GSMEM>>>(wr + 196608, nullptr, x5, vnx, nullptr, x,
                                          256, M3, sX5, 0, sN, 0, M3, 1, 0, 1, 1.0f, 0);

    ln_k<<<NB*NP, 128>>>(vnx, g2, b2, nx2, 1);

    gemm_k<<<dim3(48,4,NB), 256, GSMEM>>>(wr + 229376, wr + 262144, nx2, p3, d3, nullptr,
                                          128, M3, sN, 0, sX5, 0, M3, 1, 0, 0, 1.0f, 2);
    leaky_ew<<<NB*2*NC*NP/256, 256>>>(p3, d3, h);

    gemm_k<<<dim3(48,2,NB), 256, GSMEM>>>(wr + 294912, wr + 327680, h, p4, d4, nullptr,
                                          256, M3, sX5, 0, sN, 0, M3, 1, 0, 0, 1.0f, 1);

    final_k<<<NB*NC*NP/256, 256>>>(p4, d4, vnx, out);
}

// round 10
// speedup vs baseline: 1.3730x; 1.0037x over previous
#include <cuda_runtime.h>
#include <math.h>

#define NB 4
#define NP 2048
#define NC 128
#define ND 384
#define NH 6
#define FD 192
#define M3 (3*NP)
#define QOFF (NB*ND*M3)

__device__ float g_normx[NB*NC*3*NP];
__device__ float g_qkv[3*NB*ND*3*NP];
__device__ float g_ao[NB*ND*3*NP];
__device__ float g_G [NB*NP*1536];
__device__ float g_x5[NB*2*NC*3*NP];
__device__ float g_vnx[NB*NC*3*NP];
__device__ float g_nx2[NB*NC*3*NP];
__device__ float g_p3[NB*2*NC*3*NP];
__device__ float g_d3[NB*2*NC*3*NP];
__device__ float g_h [NB*2*NC*3*NP];
__device__ float g_p4[NB*NC*3*NP];
__device__ float g_d4[NB*NC*3*NP];
__device__ float g_cw[512*128];
__device__ float g_wr[360448];

__device__ __forceinline__ unsigned f2tf(float f) {
    unsigned u;
    asm("cvt.rna.tf32.f32 %0, %1;" : "=r"(u) : "f"(f));
    return u;
}
__device__ __forceinline__ float f2tff(float f) { return __uint_as_float(f2tf(f)); }
__device__ __forceinline__ float fexp2(float x) {
    float r;
    asm("ex2.approx.f32 %0, %1;" : "=f"(r) : "f"(x));
    return r;
}
__device__ __forceinline__ void mma8(float* d, const unsigned* a, unsigned b0, unsigned b1) {
    asm volatile("mma.sync.aligned.m16n8k8.row.col.f32.tf32.tf32.f32 "
                 "{%0,%1,%2,%3},{%4,%5,%6,%7},{%8,%9},{%0,%1,%2,%3};"
                 : "+f"(d[0]), "+f"(d[1]), "+f"(d[2]), "+f"(d[3])
                 : "r"(a[0]), "r"(a[1]), "r"(a[2]), "r"(a[3]), "r"(b0), "r"(b1));
}
__device__ __forceinline__ void cpa16(unsigned dst, const void* src) {
    asm volatile("cp.async.cg.shared.global [%0], [%1], 16;" :: "r"(dst), "l"(src));
}
__device__ __forceinline__ void cpac() { asm volatile("cp.async.commit_group;"); }
__device__ __forceinline__ void cpaw1() { asm volatile("cp.async.wait_group 1;"); }
__device__ __forceinline__ void cpaw0() { asm volatile("cp.async.wait_group 0;"); }

// ---------------- weight prep ----------------
__global__ void prep_w(const float* __restrict__ Wq, const float* __restrict__ Wk,
                       const float* __restrict__ Wv, const float* __restrict__ Wo,
                       const float* __restrict__ W2, const float* __restrict__ W3,
                       const float* __restrict__ U3, const float* __restrict__ W4,
                       const float* __restrict__ U4, float* __restrict__ wr)
{
    int i = blockIdx.x*256 + threadIdx.x;
    if (i >= 360448) return;
    float v;
    if      (i < 49152)  v = Wq[i];
    else if (i < 98304)  v = Wk[i - 49152];
    else if (i < 147456) v = Wv[i - 98304];
    else if (i < 196608) v = Wo[i - 147456];
    else if (i < 229376) v = W2[i - 196608];
    else if (i < 262144) v = W3[i - 229376];
    else if (i < 294912) v = U3[i - 262144];
    else if (i < 327680) v = W4[i - 294912];
    else                 v = U4[i - 327680];
    wr[i] = f2tff(v);
}

__global__ void prep_cw(const float* __restrict__ W1, const float* __restrict__ U1,
                        float* __restrict__ CW)
{
    int idx = blockIdx.x * 256 + threadIdx.x;
    if (idx >= 512*128) return;
    int col = idx >> 7, c = idx & 127;
    int a = col / 128, o = col % 128;
    float v;
    if      (a == 0) v = W1[o*256 + c];
    else if (a == 1) v = W1[o*256 + 128 + c] - W1[o*256 + c];
    else if (a == 2) v = U1[o*256 + c];
    else             v = U1[o*256 + 128 + c] - U1[o*256 + c];
    CW[col*128 + c] = f2tff(v);
}

// ---------------- vector-norm layernorm ----------------
__global__ __launch_bounds__(128) void ln_k(const float* __restrict__ in,
                                            const float* __restrict__ g,
                                            const float* __restrict__ bb,
                                            float* __restrict__ out, int mode)
{
    int bn = blockIdx.x;
    int b = bn >> 11, n = bn & 2047;
    int c = threadIdx.x;
    float v0, v1, v2;
    if (mode == 0) {
        const float* p = in + (long long)bn*384 + 3*c;
        v0 = p[0]; v1 = p[1]; v2 = p[2];
    } else {
        const float* p = in + ((long long)b*NC + c)*M3 + n;
        v0 = p[0]; v1 = p[2048]; v2 = p[4096];
    }
    float nrm = sqrtf(v0*v0 + v1*v1 + v2*v2 + 1e-6f);
    float s = nrm, s2 = nrm*nrm;
    for (int m = 16; m; m >>= 1) {
        s  += __shfl_xor_sync(0xffffffffu, s,  m);
        s2 += __shfl_xor_sync(0xffffffffu, s2, m);
    }
    __shared__ float sb[8];
    int w = c >> 5, lane = c & 31;
    if (!lane) { sb[w] = s; sb[4 + w] = s2; }
    __syncthreads();
    float ts  = sb[0] + sb[1] + sb[2] + sb[3];
    float ts2 = sb[4] + sb[5] + sb[6] + sb[7];
    float mu  = ts * (1.f/128.f);
    float var = ts2 * (1.f/128.f) - mu*mu;
    float nhat = (nrm - mu) / sqrtf(var + 1e-5f);
    float scale = (g[c]*nhat + bb[c]) / nrm;
    float* q = out + ((long long)b*NC + c)*M3 + n;
    q[0] = f2tff(v0*scale); q[2048] = f2tff(v1*scale); q[4096] = f2tff(v2*scale);
}

// ---------------- GEMM v4 (unchanged) ----------------
#define GSMEM (26880*4)
__global__ __launch_bounds__(256, 2) void gemm_k(
    const float* __restrict__ W, const float* __restrict__ Wb,
    const float* __restrict__ X, float* __restrict__ Y, float* __restrict__ Y2,
    const float* __restrict__ Res,
    int Cin, int ldx,
    long long xsb, long long xsi, long long ysb, long long ysi,
    int oso, int osm, int zflag, int mode, float oscale, int ysplit)
{
    extern __shared__ float smn[];
    int z = blockIdx.z;
    int b  = (zflag == 1) ? z/3 : z;
    int i3 = (zflag == 1) ? z%3 : 0;
    const float* xb = X + (long long)b*xsb + (long long)i3*xsi;
    int by = blockIdx.y;
    int o0;
    float* yb;
    float osc = oscale;
    if (zflag == 2) {
        int wsel = by / 3;
        o0 = (by % 3) * 128;
        W += wsel * 49152;
        yb = Y + (long long)wsel*QOFF + (long long)b*ysb;
        if (wsel) osc = 1.0f;
    } else if (ysplit > 0 && by >= ysplit) {
        o0 = (by - ysplit) * 128;
        W = Wb;
        yb = Y2 + (long long)b*ysb + (long long)i3*ysi;
    } else {
        o0 = by * 128;
        yb = Y + (long long)b*ysb + (long long)i3*ysi;
    }
    int m0 = blockIdx.x * 128;
    int tid = threadIdx.x;
    int wid = tid >> 5, lane = tid & 31;
    int a_ = lane >> 2, b_ = lane & 3;
    int wy = wid >> 1, wx = wid & 1;
    unsigned sm_u = (unsigned)__cvta_generic_to_shared(smn);

    float acc[2][8][4];
    #pragma unroll
    for (int i = 0; i < 2; i++)
        #pragma unroll
        for (int j = 0; j < 8; j++)
            #pragma unroll
            for (int c = 0; c < 4; c++) acc[i][j][c] = 0.f;

    int nchunk = Cin >> 5;
    int fo = tid >> 3, fk4 = (tid & 7) << 2;
    int fr = tid >> 5, fc4 = (tid & 31) << 2;

    #define GFILL(ch) do { \
        int k0 = (ch) << 5; \
        int stg = (ch) % 3; \
        unsigned swu = sm_u + (unsigned)(stg*8960*4); \
        unsigned sxu = swu + (unsigned)(4608*4); \
        cpa16(swu + (unsigned)((fo*36 + fk4)*4),        W + (long long)(o0 + fo)*Cin + k0 + fk4); \
        cpa16(swu + (unsigned)(((fo+32)*36 + fk4)*4),   W + (long long)(o0 + fo + 32)*Cin + k0 + fk4); \
        cpa16(swu + (unsigned)(((fo+64)*36 + fk4)*4),   W + (long long)(o0 + fo + 64)*Cin + k0 + fk4); \
        cpa16(swu + (unsigned)(((fo+96)*36 + fk4)*4),   W + (long long)(o0 + fo + 96)*Cin + k0 + fk4); \
        cpa16(sxu + (unsigned)((fr*136 + fc4)*4),       xb + (long long)(k0 + fr)*ldx + m0 + fc4); \
        cpa16(sxu + (unsigned)(((fr+8)*136 + fc4)*4),   xb + (long long)(k0 + fr + 8)*ldx + m0 + fc4); \
        cpa16(sxu + (unsigned)(((fr+16)*136 + fc4)*4),  xb + (long long)(k0 + fr + 16)*ldx + m0 + fc4); \
        cpa16(sxu + (unsigned)(((fr+24)*136 + fc4)*4),  xb + (long long)(k0 + fr + 24)*ldx + m0 + fc4); \
    } while (0)

    GFILL(0); cpac();
    if (nchunk > 1) GFILL(1);
    cpac();

    for (int ch = 0; ch < nchunk; ch++) {
        cpaw1();
        __syncthreads();
        int stg = ch % 3;
        const float* swb = smn + stg*8960;
        const float* sxb = swb + 4608;
        const float* pA0 = swb + (wy*32 + a_)*36 + b_;
        const float* pA1 = pA0 + 576;
        const float* pX  = sxb + b_*136 + wx*64 + a_;
        #pragma unroll
        for (int kf = 0; kf < 4; kf++) {
            unsigned A[2][4];
            A[0][0] = __float_as_uint(pA0[kf*8]);
            A[0][1] = __float_as_uint(pA0[kf*8 + 288]);
            A[0][2] = __float_as_uint(pA0[kf*8 + 4]);
            A[0][3] = __float_as_uint(pA0[kf*8 + 292]);
            A[1][0] = __float_as_uint(pA1[kf*8]);
            A[1][1] = __float_as_uint(pA1[kf*8 + 288]);
            A[1][2] = __float_as_uint(pA1[kf*8 + 4]);
            A[1][3] = __float_as_uint(pA1[kf*8 + 292]);
            #pragma unroll
            for (int nf = 0; nf < 8; nf++) {
                unsigned B0 = __float_as_uint(pX[kf*1088 + nf*8]);
                unsigned B1 = __float_as_uint(pX[kf*1088 + nf*8 + 544]);
                mma8(acc[0][nf], A[0], B0, B1);
                mma8(acc[1][nf], A[1], B0, B1);
            }
        }
        if (ch + 2 < nchunk) GFILL(ch + 2);
        cpac();
    }

    int ob = o0 + wy*32, mb = m0 + wx*64;
    if (osm == 1) {
        #pragma unroll
        for (int mf = 0; mf < 2; mf++)
            #pragma unroll
            for (int nf = 0; nf < 8; nf++) {
                int o = ob + mf*16 + a_;
                int m = mb + nf*8 + 2*b_;
                float2 v0 = make_float2(acc[mf][nf][0], acc[mf][nf][1]);
                float2 v1 = make_float2(acc[mf][nf][2], acc[mf][nf][3]);
                if (mode & 1) {
                    long long rb = (long long)b*NP*ND;
                    v0.x += Res[rb + (long long)(m & 2047)*ND + 3*o + (m >> 11)];
                    v0.y += Res[rb + (long long)((m+1) & 2047)*ND + 3*o + ((m+1) >> 11)];
                    v1.x += Res[rb + (long long)(m & 2047)*ND + 3*(o+8) + (m >> 11)];
                    v1.y += Res[rb + (long long)((m+1) & 2047)*ND + 3*(o+8) + ((m+1) >> 11)];
                }
                if (mode & 2) {
                    v0.x = f2tff(v0.x*osc); v0.y = f2tff(v0.y*osc);
                    v1.x = f2tff(v1.x*osc); v1.y = f2tff(v1.y*osc);
                }
                *(float2*)(yb + (long long)o*oso + m) = v0;
                *(float2*)(yb + (long long)(o+8)*oso + m) = v1;
            }
    } else {
        #pragma unroll
        for (int mf = 0; mf < 2; mf++)
            #pragma unroll
            for (int nf = 0; nf < 8; nf++)
                #pragma unroll
                for (int c = 0; c < 4; c++) {
                    int o = ob + mf*16 + a_ + ((c >> 1) ? 8 : 0);
                    int m = mb + nf*8 + 2*b_ + (c & 1);
                    yb[(long long)o*oso + (long long)m*osm] = acc[mf][nf][c];
                }
    }
}

// ---------------- flash v6: 3-buffer KV ring, half-exchange Sx, 3 syncs ----------------
// floats: Sx[32 frag][128] 0..4096 | Ps[32][136] 4096..8448 | al 8448..8576
//         K 8576..27008 (3x6144 swz) | V 27008..47744 (3x6912)
// Q staging (prologue only) overlaps 0..24576
#define SXF 0
#define PSF 4096
#define ALF 8448
#define KSF 8576
#define VSF 27008
#define FTC_SMEM (47744*4)

__global__ __launch_bounds__(256, 1) void flash_tc(const float* __restrict__ Q,
                                                   const float* __restrict__ K,
                                                   const float* __restrict__ V,
                                                   float* __restrict__ O)
{
    extern __shared__ float sm[];
    float* Ps   = sm + PSF;
    float* al_s = sm + ALF;
    unsigned sm_u = (unsigned)__cvta_generic_to_shared(sm);

    int n0 = blockIdx.x * 128;
    long long hb = (long long)(blockIdx.z*NH + blockIdx.y) * FD * NP;
    const float* Qb = Q + hb;
    const float* Kb = K + hb;
    const float* Vb = V + hb;
    float* Ob = O + hb;

    int tid = threadIdx.x;
    int wid = tid >> 5, lane = tid & 31;
    int a_ = lane >> 2, b_ = lane & 3;
    int qg = wid >> 1, dh = wid & 1;

    int fd8 = tid >> 3, ft4 = (tid & 7) << 2;
    #define FKV(t, bi) do { \
        int kt = (t) << 5; \
        unsigned ku = sm_u + (unsigned)((KSF + (bi)*6144)*4); \
        unsigned vu = sm_u + (unsigned)((VSF + (bi)*6912)*4); \
        _Pragma("unroll") \
        for (int i = 0; i < 6; i++) { \
            int d = fd8 + i*32; \
            cpa16(ku + (unsigned)(((d << 5) + (ft4 ^ ((d & 3) << 3)))*4), Kb + (long long)d*NP + kt + ft4); \
            cpa16(vu + (unsigned)((d*36 + ft4)*4),                        Vb + (long long)d*NP + kt + ft4); \
        } \
    } while (0)

    // prologue: Q staging at offset 0 (overlaps ring; prologue-only liveness)
    {
        int qd = tid >> 5, qc4 = (tid & 31) << 2;
        #pragma unroll
        for (int i = 0; i < 24; i++) {
            int d = qd + i*8;
            cpa16(sm_u + (unsigned)(((d << 7) + (qc4 ^ ((d & 3) << 3)))*4),
                  Qb + (long long)d*NP + n0 + qc4);
        }
    }
    cpac();
    cpaw0();
    __syncthreads();

    unsigned qreg[12][2][4];
    {
        int s8 = b_ << 3;
        int qv00 = ((qg<<5) + a_) ^ s8;
        int qv01 = ((qg<<5) + 8 + a_) ^ s8;
        int qv10 = ((qg<<5) + 16 + a_) ^ s8;
        int qv11 = ((qg<<5) + 24 + a_) ^ s8;
        const float* pQ = sm + (b_ << 7);
        #pragma unroll
        for (int kf = 0; kf < 12; kf++) {
            int qb2 = (dh*12 + kf) << 10;
            qreg[kf][0][0] = __float_as_uint(pQ[qb2 + qv00]);
            qreg[kf][0][1] = __float_as_uint(pQ[qb2 + qv01]);
            qreg[kf][0][2] = __float_as_uint(pQ[qb2 + 512 + qv00]);
            qreg[kf][0][3] = __float_as_uint(pQ[qb2 + 512 + qv01]);
            qreg[kf][1][0] = __float_as_uint(pQ[qb2 + qv10]);
            qreg[kf][1][1] = __float_as_uint(pQ[qb2 + qv11]);
            qreg[kf][1][2] = __float_as_uint(pQ[qb2 + 512 + qv10]);
            qreg[kf][1][3] = __float_as_uint(pQ[qb2 + 512 + qv11]);
        }
    }
    __syncthreads();      // all warps done reading Q staging before ring fills land

    FKV(0, 0); cpac();
    FKV(1, 1); cpac();

    int tv[4];
    {
        int s8 = b_ << 3;
        #pragma unroll
        for (int n = 0; n < 4; n++) tv[n] = ((n << 3) + a_) ^ s8;
    }

    float m_run[2] = {-1e30f, -1e30f};
    float l_run[2] = {0.f, 0.f};
    float o_acc[2][12][4];
    #pragma unroll
    for (int i = 0; i < 2; i++)
        #pragma unroll
        for (int j = 0; j < 12; j++)
            #pragma unroll
            for (int c = 0; c < 4; c++) o_acc[i][j][c] = 0.f;

    int rA = (qg<<5) + (dh<<4) + a_;
    int wslot = ((qg*2 + dh) << 2);        // this warp's write slots (other-mf)
    int rslot = ((qg*2 + (1 - dh)) << 2);  // complement read slots

    for (int t = 0; t < 64; t++) {
        cpaw1();
        __syncthreads();
        if (t + 2 < 64) FKV(t + 2, (t + 2) % 3);
        cpac();
        int bi = t % 3;
        const float* Ksb = sm + KSF + bi*6144;
        const float* Vsb = sm + VSF + bi*6912;
        const float* pK = Ksb + dh*3072 + (b_ << 5);

        // ---- QK in two 16-key passes; own rows stay in regs ----
        float sown[4][4];
        #pragma unroll
        for (int nfh = 0; nfh < 2; nfh++) {
            float s16[2][2][4];
            #pragma unroll
            for (int mf = 0; mf < 2; mf++)
                #pragma unroll
                for (int nf = 0; nf < 2; nf++)
                    #pragma unroll
                    for (int c = 0; c < 4; c++) s16[mf][nf][c] = 0.f;
            #pragma unroll
            for (int kf = 0; kf < 12; kf++) {
                int kb = kf << 8;
                unsigned B00 = __float_as_uint(pK[kb + tv[nfh*2]]);
                unsigned B01 = __float_as_uint(pK[kb + 128 + tv[nfh*2]]);
                unsigned B10 = __float_as_uint(pK[kb + tv[nfh*2+1]]);
                unsigned B11 = __float_as_uint(pK[kb + 128 + tv[nfh*2+1]]);
                mma8(s16[0][0], qreg[kf][0], B00, B01);
                mma8(s16[1][0], qreg[kf][1], B00, B01);
                mma8(s16[0][1], qreg[kf][0], B10, B11);
                mma8(s16[1][1], qreg[kf][1], B10, B11);
            }
            #pragma unroll
            for (int nf = 0; nf < 2; nf++) {
                #pragma unroll
                for (int c = 0; c < 4; c++)
                    sown[nfh*2 + nf][c] = dh ? s16[1][nf][c] : s16[0][nf][c];
                float4 oth;
                oth.x = dh ? s16[0][nf][0] : s16[1][nf][0];
                oth.y = dh ? s16[0][nf][1] : s16[1][nf][1];
                oth.z = dh ? s16[0][nf][2] : s16[1][nf][2];
                oth.w = dh ? s16[0][nf][3] : s16[1][nf][3];
                *(float4*)(sm + SXF + (wslot + nfh*2 + nf)*128 + (lane << 2)) = oth;
            }
        }
        __syncthreads();

        // ---- softmax on own 16 rows ----
        {
            float st[4][4];
            #pragma unroll
            for (int nfg = 0; nfg < 4; nfg++) {
                float4 xo = *(const float4*)(sm + SXF + (rslot + nfg)*128 + (lane << 2));
                st[nfg][0] = sown[nfg][0] + xo.x;
                st[nfg][1] = sown[nfg][1] + xo.y;
                st[nfg][2] = sown[nfg][2] + xo.z;
                st[nfg][3] = sown[nfg][3] + xo.w;
            }
            float mA = -1e30f, mB = -1e30f;
            #pragma unroll
            for (int nfg = 0; nfg < 4; nfg++) {
                mA = fmaxf(mA, fmaxf(st[nfg][0], st[nfg][1]));
                mB = fmaxf(mB, fmaxf(st[nfg][2], st[nfg][3]));
            }
            mA = fmaxf(mA, __shfl_xor_sync(0xffffffffu, mA, 1));
            mA = fmaxf(mA, __shfl_xor_sync(0xffffffffu, mA, 2));
            mB = fmaxf(mB, __shfl_xor_sync(0xffffffffu, mB, 1));
            mB = fmaxf(mB, __shfl_xor_sync(0xffffffffu, mB, 2));
            float mnA = fmaxf(m_run[0], mA);
            float mnB = fmaxf(m_run[1], mB);
            float alA = fexp2(m_run[0] - mnA);
            float alB = fexp2(m_run[1] - mnB);
            m_run[0] = mnA; m_run[1] = mnB;
            float psA = 0.f, psB = 0.f;
            #pragma unroll
            for (int nfg = 0; nfg < 4; nfg++) {
                int kcol = (nfg << 3) + (b_ << 1);
                #pragma unroll
                for (int c1 = 0; c1 < 2; c1++) {
                    float pA = fexp2(st[nfg][c1] - mnA);
                    float pB = fexp2(st[nfg][2 + c1] - mnB);
                    psA += pA; psB += pB;
                    Ps[(kcol + c1)*136 + rA] = pA;
                    Ps[(kcol + c1)*136 + rA + 8] = pB;
                }
            }
            psA += __shfl_xor_sync(0xffffffffu, psA, 1);
            psA += __shfl_xor_sync(0xffffffffu, psA, 2);
            psB += __shfl_xor_sync(0xffffffffu, psB, 1);
            psB += __shfl_xor_sync(0xffffffffu, psB, 2);
            l_run[0] = l_run[0]*alA + psA;
            l_run[1] = l_run[1]*alB + psB;
            if (b_ == 0) { al_s[rA] = alA; al_s[rA + 8] = alB; }
        }
        __syncthreads();

        // ---- rescale + PV ----
        {
            float al0 = al_s[(qg<<5) + a_];
            float al1 = al_s[(qg<<5) + 8 + a_];
            float al2 = al_s[(qg<<5) + 16 + a_];
            float al3 = al_s[(qg<<5) + 24 + a_];
            #pragma unroll
            for (int nd = 0; nd < 12; nd++) {
                o_acc[0][nd][0] *= al0; o_acc[0][nd][1] *= al0;
                o_acc[0][nd][2] *= al1; o_acc[0][nd][3] *= al1;
                o_acc[1][nd][0] *= al2; o_acc[1][nd][1] *= al2;
                o_acc[1][nd][2] *= al3; o_acc[1][nd][3] *= al3;
            }
            const float* pP = Ps + b_*136 + (qg<<5) + a_;
            const float* pV = Vsb + (dh*96 + a_)*36 + b_;
            #pragma unroll
            for (int kf = 0; kf < 4; kf++) {
                unsigned A40[4], A41[4];
                A40[0] = __float_as_uint(pP[kf*1088]);
                A40[1] = __float_as_uint(pP[kf*1088 + 8]);
                A40[2] = __float_as_uint(pP[kf*1088 + 544]);
                A40[3] = __float_as_uint(pP[kf*1088 + 552]);
                A41[0] = __float_as_uint(pP[kf*1088 + 16]);
                A41[1] = __float_as_uint(pP[kf*1088 + 24]);
                A41[2] = __float_as_uint(pP[kf*1088 + 560]);
                A41[3] = __float_as_uint(pP[kf*1088 + 568]);
                #pragma unroll
                for (int nd = 0; nd < 12; nd++) {
                    unsigned Bv0 = __float_as_uint(pV[nd*288 + kf*8]);
                    unsigned Bv1 = __float_as_uint(pV[nd*288 + kf*8 + 4]);
                    mma8(o_acc[0][nd], A40, Bv0, Bv1);
                    mma8(o_acc[1][nd], A41, Bv0, Bv1);
                }
            }
        }
        // no end sync: next top sync fences ring reuse
    }

    if (b_ == 0) {
        al_s[rA] = 1.f / l_run[0];
        al_s[rA + 8] = 1.f / l_run[1];
    }
    __syncthreads();
    {
        float i0 = al_s[(qg<<5) + a_];
        float i1 = al_s[(qg<<5) + 8 + a_];
        float i2 = al_s[(qg<<5) + 16 + a_];
        float i3 = al_s[(qg<<5) + 24 + a_];
        #pragma unroll
        for (int nd = 0; nd < 12; nd++) {
            int d0 = dh*96 + nd*8 + 2*b_;
            long long r0 = (long long)d0*NP + n0 + (qg<<5) + a_;
            Ob[r0]           = f2tff(o_acc[0][nd][0] * i0);
            Ob[r0 + NP]      = f2tff(o_acc[0][nd][1] * i0);
            Ob[r0 + 8]       = f2tff(o_acc[0][nd][2] * i1);
            Ob[r0 + NP + 8]  = f2tff(o_acc[0][nd][3] * i1);
            Ob[r0 + 16]      = f2tff(o_acc[1][nd][0] * i2);
            Ob[r0 + NP + 16] = f2tff(o_acc[1][nd][1] * i2);
            Ob[r0 + 24]      = f2tff(o_acc[1][nd][2] * i3);
            Ob[r0 + NP + 24] = f2tff(o_acc[1][nd][3] * i3);
        }
    }
}

// ---------------- kNN gather + VN-leaky + mean pool ----------------
__global__ __launch_bounds__(128) void gather_leaky(const float* __restrict__ G,
                                                    const int* __restrict__ knn,
                                                    float* __restrict__ X5)
{
    int bn = blockIdx.x;
    int b = bn >> 11, n = bn & 2047;
    int o = threadIdx.x;
    __shared__ int ridx[8];
    if (o < 8) ridx[o] = knn[((b*8 + o) << 11) + n];
    __syncthreads();
    const float* gc = G + (long long)bn*1536;
    float pc0 = gc[128 + o],        dc0 = gc[384 + o];
    float pc1 = gc[512 + 128 + o],  dc1 = gc[512 + 384 + o];
    float pc2 = gc[1024 + 128 + o], dc2 = gc[1024 + 384 + o];
    float a0 = 0.f, a1 = 0.f, a2 = 0.f;
    #pragma unroll
    for (int k = 0; k < 8; k++) {
        const float* gr = G + (long long)ridx[k]*1536;
        float p0 = gr[o] + pc0;
        float p1 = gr[512 + o] + pc1;
        float p2 = gr[1024 + o] + pc2;
        float d0 = gr[256 + o] + dc0;
        float d1 = gr[512 + 256 + o] + dc1;
        float d2 = gr[1024 + 256 + o] + dc2;
        float dot = p0*d0 + p1*d1 + p2*d2;
        if (dot < 0.f) {
            float f = 0.8f * dot / (d0*d0 + d1*d1 + d2*d2 + 1e-6f);
            p0 -= f*d0; p1 -= f*d1; p2 -= f*d2;
        }
        a0 += p0; a1 += p1; a2 += p2;
    }
    float* y = X5 + (long long)b*(2*NC*M3) + (long long)(128 + o)*M3 + n;
    y[0] = f2tff(a0*0.125f); y[2048] = f2tff(a1*0.125f); y[4096] = f2tff(a2*0.125f);
}

// ---------------- elementwise VN-leaky ----------------
__global__ void leaky_ew(const float* __restrict__ P, const float* __restrict__ D,
                         float* __restrict__ Y)
{
    int idx = blockIdx.x*256 + threadIdx.x;
    int n = idx & 2047;
    int bo = idx >> 11;
    long long base = ((long long)bo*3 << 11) + n;
    float p0 = P[base], p1 = P[base + 2048], p2 = P[base + 4096];
    float d0 = D[base], d1 = D[base + 2048], d2 = D[base + 4096];
    float dot = p0*d0 + p1*d1 + p2*d2;
    if (dot < 0.f) {
        float f = 0.8f * dot / (d0*d0 + d1*d1 + d2*d2 + 1e-6f);
        p0 -= f*d0; p1 -= f*d1; p2 -= f*d2;
    }
    Y[base] = f2tff(p0); Y[base + 2048] = f2tff(p1); Y[base + 4096] = f2tff(p2);
}

// ---------------- conv4 leaky + residual + output transpose ----------------
__global__ void final_k(const float* __restrict__ P, const float* __restrict__ D,
                        const float* __restrict__ vnx, float* __restrict__ out)
{
    int idx = blockIdx.x*256 + threadIdx.x;
    int n = idx & 2047;
    int o = (idx >> 11) & 127;
    int b = idx >> 18;
    long long base2 = (((long long)(b*NC + o))*3 << 11) + n;
    float p0 = P[base2], p1 = P[base2 + 2048], p2 = P[base2 + 4096];
    float d0 = D[base2], d1 = D[base2 + 2048], d2 = D[base2 + 4096];
    float dot = p0*d0 + p1*d1 + p2*d2;
    if (dot < 0.f) {
        float f = 0.8f * dot / (d0*d0 + d1*d1 + d2*d2 + 1e-6f);
        p0 -= f*d0; p1 -= f*d1; p2 -= f*d2;
    }
    float r0 = vnx[base2], r1 = vnx[base2 + 2048], r2 = vnx[base2 + 4096];
    float* q = out + ((long long)(b*NP + n))*ND + 3*o;
    q[0] = r0 + p0; q[1] = r1 + p1; q[2] = r2 + p2;
}

// ---------------- host ----------------
extern "C" void kernel_launch(void* const* d_in, const int* in_sizes, int n_in,
                              void* d_out, int out_size)
{
    (void)in_sizes; (void)n_in; (void)out_size;
    const float* x  = (const float*)d_in[0];
    const int* knn  = (const int*)d_in[1];
    const float* g1 = (const float*)d_in[2];
    const float* b1 = (const float*)d_in[3];
    const float* g2 = (const float*)d_in[4];
    const float* b2 = (const float*)d_in[5];
    const float* Wq = (const float*)d_in[6];
    const float* Wk = (const float*)d_in[7];
    const float* Wv = (const float*)d_in[8];
    const float* Wo = (const float*)d_in[9];
    const float* W1 = (const float*)d_in[10];
    const float* U1 = (const float*)d_in[11];
    const float* W2 = (const float*)d_in[12];
    const float* W3 = (const float*)d_in[13];
    const float* U3 = (const float*)d_in[14];
    const float* W4 = (const float*)d_in[15];
    const float* U4 = (const float*)d_in[16];
    float* out = (float*)d_out;

    float *normx,*qkv,*ao,*G,*x5,*vnx,*nx2,*p3,*d3,*h,*p4,*d4,*cw,*wr;
    cudaGetSymbolAddress((void**)&normx, g_normx);
    cudaGetSymbolAddress((void**)&qkv, g_qkv);
    cudaGetSymbolAddress((void**)&ao, g_ao);
    cudaGetSymbolAddress((void**)&G,  g_G);
    cudaGetSymbolAddress((void**)&x5, g_x5);
    cudaGetSymbolAddress((void**)&vnx, g_vnx);
    cudaGetSymbolAddress((void**)&nx2, g_nx2);
    cudaGetSymbolAddress((void**)&p3, g_p3);
    cudaGetSymbolAddress((void**)&d3, g_d3);
    cudaGetSymbolAddress((void**)&h,  g_h);
    cudaGetSymbolAddress((void**)&p4, g_p4);
    cudaGetSymbolAddress((void**)&d4, g_d4);
    cudaGetSymbolAddress((void**)&cw, g_cw);
    cudaGetSymbolAddress((void**)&wr, g_wr);

    cudaFuncSetAttribute(flash_tc, cudaFuncAttributeMaxDynamicSharedMemorySize, FTC_SMEM);
    cudaFuncSetAttribute(gemm_k, cudaFuncAttributeMaxDynamicSharedMemorySize, GSMEM);

    prep_w<<<1408, 256>>>(Wq, Wk, Wv, Wo, W2, W3, U3, W4, U4, wr);
    prep_cw<<<256, 256>>>(W1, U1, cw);
    ln_k<<<NB*NP, 128>>>(x, g1, b1, normx, 0);

    long long sN = (long long)NC*M3;
    long long sQ = (long long)ND*M3;
    long long sX5 = (long long)2*NC*M3;
    const float qsc = 0.125f * 1.44269504088896f;

    gemm_k<<<dim3(48,9,NB), 256, GSMEM>>>(wr, nullptr, normx, qkv, nullptr, nullptr,
                                          128, M3, sN, 0, sQ, 0, M3, 1, 2, 2, qsc, 0);

    flash_tc<<<dim3(16, NH, NB), 256, FTC_SMEM>>>(qkv, qkv + QOFF, qkv + 2*QOFF, ao);

    gemm_k<<<dim3(48,1,NB), 256, GSMEM>>>(wr + 147456, nullptr, ao, x5, nullptr, nullptr,
                                          384, M3, sQ, 0, sX5, 0, M3, 1, 0, 2, 1.0f, 0);

    gemm_k<<<dim3(16,4,12), 256, GSMEM>>>(cw, nullptr, normx, G, nullptr, nullptr,
                                          128, M3, sN, 2048, (long long)NP*1536, 512, 1, 1536, 1, 0, 1.0f, 0);
    gather_leaky<<<NB*NP, 128>>>(G, knn, x5);

    gemm_k<<<dim3(48,1,NB), 256, GSMEM>>>(wr + 196608, nullptr, x5, vnx, nullptr, x,
                                          256, M3, sX5, 0, sN, 0, M3, 1, 0, 1, 1.0f, 0);

    ln_k<<<NB*NP, 128>>>(vnx, g2, b2, nx2, 1);

    gemm_k<<<dim3(48,4,NB), 256, GSMEM>>>(wr + 229376, wr + 262144, nx2, p3, d3, nullptr,
                                          128, M3, sN, 0, sX5, 0, M3, 1, 0, 0, 1.0f, 2);
    leaky_ew<<<NB*2*NC*NP/256, 256>>>(p3, d3, h);

    gemm_k<<<dim3(48,2,NB), 256, GSMEM>>>(wr + 294912, wr + 327680, h, p4, d4, nullptr,
                                          256, M3, sX5, 0, sN, 0, M3, 1, 0, 0, 1.0f, 1);

    final_k<<<NB*NC*NP/256, 256>>>(p4, d4, vnx, out);
}